// round 1
// baseline (speedup 1.0000x reference)
#include <cuda_runtime.h>

#define D 256
#define Lh 64
#define Bh 2
#define Nh 10
#define NQh 50
#define Mh 1000
#define NSUP 20
#define NQRY 100
#define NTILE 120
#define PITCH 257
#define PA 65
#define TILE_ELEMS (Lh*D)

// ---------------- scratch (device globals; no allocations allowed) ----------------
__device__ float g_sN[NSUP*TILE_ELEMS];
__device__ float g_qN[NQRY*TILE_ELEMS];
__device__ float g_WT [4*D*D];   // proj_W transposed: [c][j], c<1024, j<256
__device__ float g_W1T[4*D*D];   // W1 transposed
__device__ float g_base[NTILE*TILE_ELEMS]; // x @ W0^T + proj_b per unique tile
__device__ float g_logits[Mh];

// Shared-memory layout (floats) for the pair kernel
#define SM_S    0
#define SM_Q    (SM_S + Lh*PITCH)
#define SM_A    (SM_Q + Lh*PITCH)
#define SM_ATT  (SM_A + Lh*PITCH)
#define SM_PMAX (SM_ATT + Lh*PA)
#define SM_PSUM (SM_PMAX + 4*D)
#define SM_POOL (SM_PSUM + 4*D)     // 1024: [0..511]=q_pool, [512..1023]=s_pool
#define SM_RMAX (SM_POOL + 1024)
#define SM_RSUM (SM_RMAX + 64)
#define SM_CMAX (SM_RSUM + 64)
#define SM_CSUM (SM_CMAX + 64)
#define SM_RED  (SM_CSUM + 64)
#define SM_TOTAL (SM_RED + 32)
#define SMEM_PAIR_BYTES (SM_TOTAL*4)
#define SMEM_BASE_BYTES (Lh*PITCH*4)

// mish(x) = x * tanh(softplus(x)) = x * (u^2+2u)/(u^2+2u+2), u = e^x  (no cancellation)
__device__ __forceinline__ float mishf(float x){
    if (x > 20.0f) return x;
    float u = __expf(x);
    float v = u*u + 2.0f*u;
    return x * v / (v + 2.0f);
}

__device__ __forceinline__ float blockSum256(float v, float* red, int t){
    #pragma unroll
    for (int o = 16; o > 0; o >>= 1) v += __shfl_xor_sync(0xffffffffu, v, o);
    if ((t & 31) == 0) red[t >> 5] = v;
    __syncthreads();
    float s = red[0]+red[1]+red[2]+red[3]+red[4]+red[5]+red[6]+red[7];
    __syncthreads();
    return s;
}

// ---------------- kernel A: row LayerNorm of support & query ----------------
__global__ void k_ln(const float* __restrict__ sup, const float* __restrict__ qry,
                     const float* __restrict__ gg, const float* __restrict__ bb){
    __shared__ float rs[8], rq[8];
    int r = blockIdx.x, t = threadIdx.x;
    const float* src; float* dst;
    const int nsr = NSUP*Lh;
    if (r < nsr){ src = sup + (size_t)r*D; dst = g_sN + (size_t)r*D; }
    else        { src = qry + (size_t)(r-nsr)*D; dst = g_qN + (size_t)(r-nsr)*D; }
    float x = src[t];
    float s = x, q = x*x;
    #pragma unroll
    for (int o = 16; o > 0; o >>= 1){
        s += __shfl_xor_sync(0xffffffffu, s, o);
        q += __shfl_xor_sync(0xffffffffu, q, o);
    }
    if ((t & 31) == 0){ rs[t>>5] = s; rq[t>>5] = q; }
    __syncthreads();
    float S = 0.f, Q2 = 0.f;
    #pragma unroll
    for (int w = 0; w < 8; w++){ S += rs[w]; Q2 += rq[w]; }
    float mu  = S  * (1.0f/D);
    float var = Q2 * (1.0f/D) - mu*mu;
    float inv = rsqrtf(var + 1e-5f);
    dst[t] = (x - mu)*inv*gg[t] + bb[t];
}

// ---------------- kernel B: transpose weights [256][1024] -> [1024][256] ----------------
__global__ void k_transpose(const float* __restrict__ W, int which){
    int c = blockIdx.x, j = threadIdx.x;
    float v = W[(size_t)j*1024 + c];
    if (which) g_W1T[c*D + j] = v; else g_WT[c*D + j] = v;
}

// ---------------- kernel C: per-tile base = x @ W0^T + proj_b ----------------
__global__ void __launch_bounds__(256) k_base(const float* __restrict__ pb){
    extern __shared__ float smx[];
    int tile = blockIdx.x, t = threadIdx.x;
    const float* src = (tile < NSUP) ? (g_sN + (size_t)tile*TILE_ELEMS)
                                     : (g_qN + (size_t)(tile-NSUP)*TILE_ELEMS);
    for (int idx = t; idx < TILE_ELEMS; idx += 256){
        int row = idx >> 8, col = idx & 255;
        smx[row*PITCH + col] = src[idx];
    }
    __syncthreads();
    const int j4 = (t & 63)*4, lq = t >> 6;
    float4 bias = *(const float4*)(pb + j4);
    float4 acc[16];
    #pragma unroll
    for (int i = 0; i < 16; i++) acc[i] = bias;
    for (int c = 0; c < 256; c++){
        float4 w0 = *(const float4*)(g_WT + c*D + j4);
        #pragma unroll
        for (int i = 0; i < 16; i++){
            float x = smx[(lq*16+i)*PITCH + c];
            acc[i].x += x*w0.x; acc[i].y += x*w0.y;
            acc[i].z += x*w0.z; acc[i].w += x*w0.w;
        }
    }
    float* dst = g_base + (size_t)tile*TILE_ELEMS;
    #pragma unroll
    for (int i = 0; i < 16; i++)
        *(float4*)(dst + (lq*16+i)*D + j4) = acc[i];
}

// ---------------- projection phase (shared by S and Q sides) ----------------
__device__ __forceinline__ void proj_phase(
    const float* __restrict__ xt, const float* __restrict__ at,
    const float* __restrict__ basep,
    float* pmax, float* psum, float* pool_out,
    const float* __restrict__ ln2g, const float* __restrict__ ln2b,
    float* red, int t)
{
    const int j4 = (t & 63)*4;
    const int lq = t >> 6;
    float4 acc[16];
    #pragma unroll
    for (int i = 0; i < 16; i++)
        acc[i] = *(const float4*)(basep + (lq*16+i)*D + j4);
    const float* xrow = xt + (lq*16)*PITCH;
    const float* arow = at + (lq*16)*PITCH;
    for (int c = 0; c < 256; c++){
        float4 w1 = *(const float4*)(g_WT + (256+c)*D + j4);
        float4 w2 = *(const float4*)(g_WT + (512+c)*D + j4);
        float4 w3 = *(const float4*)(g_WT + (768+c)*D + j4);
        #pragma unroll
        for (int i = 0; i < 16; i++){
            float x = xrow[i*PITCH + c];
            float a = arow[i*PITCH + c];
            float e2 = fabsf(x - a);
            float e3 = x * a;
            acc[i].x += a*w1.x + e2*w2.x + e3*w3.x;
            acc[i].y += a*w1.y + e2*w2.y + e3*w3.y;
            acc[i].z += a*w1.z + e2*w2.z + e3*w3.z;
            acc[i].w += a*w1.w + e2*w2.w + e3*w3.w;
        }
    }
    float mx0=-3.4e38f, mx1=-3.4e38f, mx2=-3.4e38f, mx3=-3.4e38f;
    float s0=0.f, s1=0.f, s2=0.f, s3=0.f;
    #pragma unroll
    for (int i = 0; i < 16; i++){
        float v0 = mishf(acc[i].x), v1 = mishf(acc[i].y);
        float v2 = mishf(acc[i].z), v3 = mishf(acc[i].w);
        mx0 = fmaxf(mx0, v0); s0 += v0;
        mx1 = fmaxf(mx1, v1); s1 += v1;
        mx2 = fmaxf(mx2, v2); s2 += v2;
        mx3 = fmaxf(mx3, v3); s3 += v3;
    }
    pmax[lq*D + j4+0] = mx0; pmax[lq*D + j4+1] = mx1;
    pmax[lq*D + j4+2] = mx2; pmax[lq*D + j4+3] = mx3;
    psum[lq*D + j4+0] = s0;  psum[lq*D + j4+1] = s1;
    psum[lq*D + j4+2] = s2;  psum[lq*D + j4+3] = s3;
    __syncthreads();
    {
        float m4 = fmaxf(fmaxf(pmax[t], pmax[D+t]), fmaxf(pmax[2*D+t], pmax[3*D+t]));
        float sm = psum[t] + psum[D+t] + psum[2*D+t] + psum[3*D+t];
        pool_out[t]     = m4;
        pool_out[D + t] = sm * (1.0f/(float)Lh);
    }
    __syncthreads();
    float v0 = pool_out[t], v1 = pool_out[D + t];
    float S  = blockSum256(v0 + v1,       red, t);
    float SS = blockSum256(v0*v0 + v1*v1, red, t);
    float mean = S  * (1.0f/512.0f);
    float var  = SS * (1.0f/512.0f) - mean*mean;
    float inv  = rsqrtf(var + 1e-5f);
    pool_out[t]     = (v0 - mean)*inv*ln2g[t]     + ln2b[t];
    pool_out[D + t] = (v1 - mean)*inv*ln2g[D + t] + ln2b[D + t];
    __syncthreads();
}

// ---------------- kernel D: one CTA per (query, support) pair ----------------
__global__ void __launch_bounds__(256, 1) k_pair(
    const float* __restrict__ ln2g, const float* __restrict__ ln2b,
    const float* __restrict__ W2,  const float* __restrict__ b2,
    const float* __restrict__ W3,  const float* __restrict__ b3,
    const float* __restrict__ b1v)
{
    extern __shared__ float sm[];
    float* s_t  = sm + SM_S;
    float* q_t  = sm + SM_Q;
    float* a_t  = sm + SM_A;
    float* att  = sm + SM_ATT;
    float* pmax = sm + SM_PMAX;
    float* psum = sm + SM_PSUM;
    float* pool = sm + SM_POOL;
    float* rmax = sm + SM_RMAX;
    float* rsum = sm + SM_RSUM;
    float* cmax = sm + SM_CMAX;
    float* csum = sm + SM_CSUM;
    float* red  = sm + SM_RED;

    const int m = blockIdx.x;
    const int b = m / (NQh*Nh);
    const int rem = m % (NQh*Nh);
    const int iq = rem / Nh;
    const int n  = rem % Nh;
    const int sIdx = b*Nh + n;      // K = 1
    const int qIdx = b*NQh + iq;
    const int t = threadIdx.x;

    // load tiles into pitched smem
    {
        const float* sp = g_sN + (size_t)sIdx*TILE_ELEMS;
        const float* qp = g_qN + (size_t)qIdx*TILE_ELEMS;
        for (int idx = t; idx < TILE_ELEMS; idx += 256){
            int row = idx >> 8, col = idx & 255;
            s_t[row*PITCH + col] = sp[idx];
            q_t[row*PITCH + col] = qp[idx];
        }
    }
    __syncthreads();

    // att[l][k] = s[l] . q[k]
    {
        const int k = t & 63, l0 = t >> 6;
        float acc[16];
        #pragma unroll
        for (int i = 0; i < 16; i++) acc[i] = 0.f;
        const float* qrow = q_t + k*PITCH;
        #pragma unroll 4
        for (int d = 0; d < 256; d++){
            float qv = qrow[d];
            #pragma unroll
            for (int i = 0; i < 16; i++)
                acc[i] += s_t[(l0 + 4*i)*PITCH + d] * qv;
        }
        #pragma unroll
        for (int i = 0; i < 16; i++)
            att[(l0 + 4*i)*PA + k] = acc[i];
    }
    __syncthreads();

    // row / column maxima
    if (t < 64){
        float mx = -3.4e38f;
        const float* row = att + t*PA;
        #pragma unroll 8
        for (int k2 = 0; k2 < 64; k2++) mx = fmaxf(mx, row[k2]);
        rmax[t] = mx;
    } else if (t < 128){
        int k = t - 64;
        float mx = -3.4e38f;
        for (int l = 0; l < 64; l++) mx = fmaxf(mx, att[l*PA + k]);
        cmax[k] = mx;
    }
    __syncthreads();

    // att := E = exp(att - rmax[l])  (row-shifted exponentials)
    {
        const int k = t & 63, l0 = t >> 6;
        #pragma unroll
        for (int i = 0; i < 16; i++){
            int l = l0 + 4*i;
            att[l*PA + k] = __expf(att[l*PA + k] - rmax[l]);
        }
    }
    __syncthreads();

    // row sums (reciprocal) and column sums (reciprocal, rebased to cmax)
    if (t < 64){
        float s = 0.f;
        const float* row = att + t*PA;
        #pragma unroll 8
        for (int k2 = 0; k2 < 64; k2++) s += row[k2];
        rsum[t] = 1.0f / s;
    } else if (t < 128){
        int k = t - 64;
        float cm = cmax[k];
        float s = 0.f;
        for (int l = 0; l < 64; l++){
            float h = __expf(0.5f*(rmax[l] - cm));   // split to avoid overflow
            s += att[l*PA + k] * h * h;
        }
        csum[k] = 1.0f / s;
    }
    __syncthreads();

    // s_att[l][d] = (sum_k E[l][k] * q[k][d]) / rsum
    {
        const int d = t;
        for (int lb = 0; lb < 16; lb++){
            float a0=0.f, a1=0.f, a2=0.f, a3=0.f;
            #pragma unroll 4
            for (int k = 0; k < 64; k++){
                float qv = q_t[k*PITCH + d];
                a0 += att[(lb*4+0)*PA + k] * qv;
                a1 += att[(lb*4+1)*PA + k] * qv;
                a2 += att[(lb*4+2)*PA + k] * qv;
                a3 += att[(lb*4+3)*PA + k] * qv;
            }
            a_t[(lb*4+0)*PITCH + d] = a0 * rsum[lb*4+0];
            a_t[(lb*4+1)*PITCH + d] = a1 * rsum[lb*4+1];
            a_t[(lb*4+2)*PITCH + d] = a2 * rsum[lb*4+2];
            a_t[(lb*4+3)*PITCH + d] = a3 * rsum[lb*4+3];
        }
    }
    __syncthreads();

    // phase S: enhanced projection + pool + LN -> pool[512..1023]
    proj_phase(s_t, a_t, g_base + (size_t)sIdx*TILE_ELEMS,
               pmax, psum, pool + 512, ln2g, ln2b, red, t);

    // att := P_col = exp(att_raw - cmax[k]) / colsum  (column softmax)
    {
        const int k = t & 63, l0 = t >> 6;
        float ci = csum[k], cm = cmax[k];
        #pragma unroll
        for (int i = 0; i < 16; i++){
            int l = l0 + 4*i;
            float h = __expf(0.5f*(rmax[l] - cm));
            att[l*PA + k] = att[l*PA + k] * h * h * ci;
        }
    }
    __syncthreads();

    // q_att[k][d] = sum_l P_col[l][k] * s[l][d]
    {
        const int d = t;
        for (int kb = 0; kb < 16; kb++){
            float a0=0.f, a1=0.f, a2=0.f, a3=0.f;
            #pragma unroll 4
            for (int l = 0; l < 64; l++){
                float sv = s_t[l*PITCH + d];
                a0 += att[l*PA + kb*4+0] * sv;
                a1 += att[l*PA + kb*4+1] * sv;
                a2 += att[l*PA + kb*4+2] * sv;
                a3 += att[l*PA + kb*4+3] * sv;
            }
            a_t[(kb*4+0)*PITCH + d] = a0;
            a_t[(kb*4+1)*PITCH + d] = a1;
            a_t[(kb*4+2)*PITCH + d] = a2;
            a_t[(kb*4+3)*PITCH + d] = a3;
        }
    }
    __syncthreads();

    // phase Q -> pool[0..511]
    proj_phase(q_t, a_t, g_base + (size_t)(NSUP + qIdx)*TILE_ELEMS,
               pmax, psum, pool, ln2g, ln2b, red, t);

    // MLP head: cat = [q_pool | s_pool] (1024); h1 = mish(cat @ W1^T + b1)
    {
        float accm = b1v[t];
        #pragma unroll 4
        for (int c = 0; c < 1024; c++)
            accm += pool[c] * g_W1T[c*D + t];
        float hv = mishf(accm);
        float part = hv * W2[t];
        float tot = blockSum256(part, red, t);
        if (t == 0){
            float h = tot + b2[0];
            g_logits[m] = mishf(h)*W3[0] + b3[0];
        }
    }
}

// ---------------- kernel E: min-append, logits layout, argmax ----------------
__global__ void k_final(float* __restrict__ out, int out_size){
    int u = threadIdx.x;
    if (u >= Bh*NQh) return;
    float v[Nh];
    float mn = 3.4e38f;
    #pragma unroll
    for (int n2 = 0; n2 < Nh; n2++){
        v[n2] = g_logits[u*Nh + n2];
        mn = fminf(mn, v[n2]);
    }
    if (out_size >= 1100){
        float best = -3.4e38f; int bi = 0;
        #pragma unroll
        for (int n2 = 0; n2 < Nh; n2++){
            out[u*(Nh+1) + n2] = v[n2];
            if (v[n2] > best){ best = v[n2]; bi = n2; }
        }
        out[u*(Nh+1) + Nh] = mn - 1.0f;   // min - 1, never the argmax
        if (out_size >= 1200) out[Bh*NQh*(Nh+1) + u] = (float)bi;
    } else if (out_size == Bh*NQh){
        // pred-only output (int32)
        float best = -3.4e38f; int bi = 0;
        #pragma unroll
        for (int n2 = 0; n2 < Nh; n2++)
            if (v[n2] > best){ best = v[n2]; bi = n2; }
        ((int*)out)[u] = bi;
    }
}

// ---------------- launch ----------------
extern "C" void kernel_launch(void* const* d_in, const int* in_sizes, int n_in,
                              void* d_out, int out_size)
{
    const float* support = (const float*)d_in[0];
    const float* query   = (const float*)d_in[1];
    const float* ln_g    = (const float*)d_in[2];
    const float* ln_b    = (const float*)d_in[3];
    const float* ln2_g   = (const float*)d_in[4];
    const float* ln2_b   = (const float*)d_in[5];
    const float* proj_W  = (const float*)d_in[6];
    const float* proj_b  = (const float*)d_in[7];
    const float* W1      = (const float*)d_in[8];
    const float* b1      = (const float*)d_in[9];
    const float* W2      = (const float*)d_in[10];
    const float* b2      = (const float*)d_in[11];
    const float* W3      = (const float*)d_in[12];
    const float* b3      = (const float*)d_in[13];

    cudaFuncSetAttribute(k_pair, cudaFuncAttributeMaxDynamicSharedMemorySize, SMEM_PAIR_BYTES);
    cudaFuncSetAttribute(k_base, cudaFuncAttributeMaxDynamicSharedMemorySize, SMEM_BASE_BYTES);

    k_ln<<<(NSUP + NQRY)*Lh, 256>>>(support, query, ln_g, ln_b);
    k_transpose<<<1024, 256>>>(proj_W, 0);
    k_transpose<<<1024, 256>>>(W1, 1);
    k_base<<<NTILE, 256, SMEM_BASE_BYTES>>>(proj_b);
    k_pair<<<Mh, 256, SMEM_PAIR_BYTES>>>(ln2_g, ln2_b, W2, b2, W3, b3, b1);
    k_final<<<1, 128>>>((float*)d_out, out_size);
}

// round 2
// speedup vs baseline: 2.0420x; 2.0420x over previous
#include <cuda_runtime.h>

#define D 256
#define Lh 64
#define Bh 2
#define Nh 10
#define NQh 50
#define Mh 1000
#define NSUP 20
#define NQRY 100
#define NTILE 120
#define PITCH 257
#define PA 65
#define TILE_ELEMS (Lh*D)

// ---------------- scratch (device globals; no allocations allowed) ----------------
__device__ float g_sN[NSUP*TILE_ELEMS];
__device__ float g_qN[NQRY*TILE_ELEMS];
__device__ float g_W1T[4*D*D];                  // W1 transposed (for MLP head)
__device__ float g_Wm[32*4*32*128];             // proj_W in mma-fragment order, hi/lo pairs
__device__ float g_base[NTILE*TILE_ELEMS];      // x @ W0^T + proj_b per unique tile
__device__ float g_logits[Mh];

// Shared-memory layout (floats) for the pair kernel
#define SM_S    0
#define SM_Q    (SM_S + Lh*PITCH)
#define SM_A    (SM_Q + Lh*PITCH)
#define SM_ATT  (SM_A + Lh*PITCH)
#define SM_PMAX (SM_ATT + Lh*PA)
#define SM_PSUM (SM_PMAX + 4*D)
#define SM_POOL (SM_PSUM + 4*D)     // 1024: [0..511]=q_pool, [512..1023]=s_pool
#define SM_RMAX (SM_POOL + 1024)
#define SM_RSUM (SM_RMAX + 64)
#define SM_CMAX (SM_RSUM + 64)
#define SM_CSUM (SM_CMAX + 64)
#define SM_RED  (SM_CSUM + 64)
#define SM_TOTAL (SM_RED + 32)
#define SMEM_PAIR_BYTES (SM_TOTAL*4)
#define SMEM_BASE_BYTES (Lh*PITCH*4)

// ---------------- tf32 helpers ----------------
__device__ __forceinline__ unsigned tf32u(float x){
    unsigned r; asm("cvt.rna.tf32.f32 %0, %1;" : "=r"(r) : "f"(x)); return r;
}
__device__ __forceinline__ void hilo(float x, unsigned& h, unsigned& l){
    h = tf32u(x);
    l = tf32u(x - __uint_as_float(h));
}
__device__ __forceinline__ void mma8(float* c, const unsigned* a, const unsigned* b){
    asm volatile("mma.sync.aligned.m16n8k8.row.col.f32.tf32.tf32.f32 "
        "{%0,%1,%2,%3}, {%4,%5,%6,%7}, {%8,%9}, {%0,%1,%2,%3};\n"
        : "+f"(c[0]), "+f"(c[1]), "+f"(c[2]), "+f"(c[3])
        : "r"(a[0]), "r"(a[1]), "r"(a[2]), "r"(a[3]), "r"(b[0]), "r"(b[1]));
}

// mish(x) = x * tanh(softplus(x)) = x * (u^2+2u)/(u^2+2u+2), u = e^x
__device__ __forceinline__ float mishf(float x){
    if (x > 20.0f) return x;
    float u = __expf(x);
    float v = u*u + 2.0f*u;
    return x * v / (v + 2.0f);
}

__device__ __forceinline__ float blockSum256(float v, float* red, int t){
    #pragma unroll
    for (int o = 16; o > 0; o >>= 1) v += __shfl_xor_sync(0xffffffffu, v, o);
    if ((t & 31) == 0) red[t >> 5] = v;
    __syncthreads();
    float s = red[0]+red[1]+red[2]+red[3]+red[4]+red[5]+red[6]+red[7];
    __syncthreads();
    return s;
}

// ---------------- kernel A: row LayerNorm of support & query ----------------
__global__ void k_ln(const float* __restrict__ sup, const float* __restrict__ qry,
                     const float* __restrict__ gg, const float* __restrict__ bb){
    __shared__ float rs[8], rq[8];
    int r = blockIdx.x, t = threadIdx.x;
    const float* src; float* dst;
    const int nsr = NSUP*Lh;
    if (r < nsr){ src = sup + (size_t)r*D; dst = g_sN + (size_t)r*D; }
    else        { src = qry + (size_t)(r-nsr)*D; dst = g_qN + (size_t)(r-nsr)*D; }
    float x = src[t];
    float s = x, q = x*x;
    #pragma unroll
    for (int o = 16; o > 0; o >>= 1){
        s += __shfl_xor_sync(0xffffffffu, s, o);
        q += __shfl_xor_sync(0xffffffffu, q, o);
    }
    if ((t & 31) == 0){ rs[t>>5] = s; rq[t>>5] = q; }
    __syncthreads();
    float S = 0.f, Q2 = 0.f;
    #pragma unroll
    for (int w = 0; w < 8; w++){ S += rs[w]; Q2 += rq[w]; }
    float mu  = S  * (1.0f/D);
    float var = Q2 * (1.0f/D) - mu*mu;
    float inv = rsqrtf(var + 1e-5f);
    dst[t] = (x - mu)*inv*gg[t] + bb[t];
}

// ---------------- kernel B: transpose W1 [256][1024] -> [1024][256] ----------------
__global__ void k_transposeW1(const float* __restrict__ W){
    int c = blockIdx.x, j = threadIdx.x;
    g_W1T[c*D + j] = W[(size_t)j*1024 + c];
}

// ---------------- kernel B2: reorder proj_W into mma-fragment order with hi/lo ----------------
// layout: g_Wm[(((kb*4 + w)*32) + jt)*128 + lane*4] = {hi(k), hi(k+4), lo(k), lo(k+4)}
// w = 0,1,2 -> proj blocks cols 256..511, 512..767, 768..1023;  w = 3 -> block 0 (base)
__global__ void k_prepw(const float* __restrict__ pw){
    int idx = blockIdx.x*256 + threadIdx.x;     // 131072 total
    int lane = idx & 31;
    int jt   = (idx >> 5) & 31;
    int w    = (idx >> 10) & 3;
    int kb   = idx >> 12;
    int tig = lane & 3, gid = lane >> 2;
    int j = jt*8 + gid;
    int cblk = (w == 3) ? 0 : (w + 1);
    size_t base = (size_t)j*1024 + cblk*256 + kb*8 + tig;
    float w0 = pw[base];
    float w1 = pw[base + 4];
    unsigned h0,l0,h1,l1; hilo(w0,h0,l0); hilo(w1,h1,l1);
    float4 v;
    v.x = __uint_as_float(h0); v.y = __uint_as_float(h1);
    v.z = __uint_as_float(l0); v.w = __uint_as_float(l1);
    *(float4*)(g_Wm + (size_t)idx*4) = v;
}

// ---------------- kernel C: per-tile base = x @ W0^T + proj_b  (3xTF32 mma) ----------------
__global__ void __launch_bounds__(256,1) k_base(const float* __restrict__ pb){
    extern __shared__ float smx[];
    int tile = blockIdx.x, t = threadIdx.x;
    const float* src = (tile < NSUP) ? (g_sN + (size_t)tile*TILE_ELEMS)
                                     : (g_qN + (size_t)(tile-NSUP)*TILE_ELEMS);
    for (int idx = t; idx < TILE_ELEMS; idx += 256){
        int row = idx >> 8, col = idx & 255;
        smx[row*PITCH + col] = src[idx];
    }
    __syncthreads();

    const int lane = t & 31, warp = t >> 5;
    const int gid = lane >> 2, tig = lane & 3;
    const int wm = warp >> 2, wn = warp & 3;

    float c[2][8][4];
    #pragma unroll
    for (int nt = 0; nt < 8; nt++){
        int col = wn*64 + nt*8 + 2*tig;
        float b0 = pb[col], b1 = pb[col+1];
        #pragma unroll
        for (int mt = 0; mt < 2; mt++){
            c[mt][nt][0] = b0; c[mt][nt][1] = b1;
            c[mt][nt][2] = b0; c[mt][nt][3] = b1;
        }
    }
    for (int kb = 0; kb < 32; kb++){
        unsigned ah[2][4], al[2][4];
        #pragma unroll
        for (int mt = 0; mt < 2; mt++){
            int rbase = wm*32 + mt*16 + gid;
            #pragma unroll
            for (int p = 0; p < 4; p++){
                int rr = rbase + (p & 1)*8;
                int cc = kb*8 + tig + (p >> 1)*4;
                hilo(smx[rr*PITCH + cc], ah[mt][p], al[mt][p]);
            }
        }
        #pragma unroll
        for (int nt = 0; nt < 8; nt++){
            float4 wv = *(const float4*)(g_Wm + ((size_t)((kb*4 + 3)*32 + wn*8 + nt))*128 + lane*4);
            unsigned bh[2] = { __float_as_uint(wv.x), __float_as_uint(wv.y) };
            unsigned bl[2] = { __float_as_uint(wv.z), __float_as_uint(wv.w) };
            #pragma unroll
            for (int mt = 0; mt < 2; mt++){
                mma8(c[mt][nt], ah[mt], bh);
                mma8(c[mt][nt], ah[mt], bl);
                mma8(c[mt][nt], al[mt], bh);
            }
        }
    }
    float* dst = g_base + (size_t)tile*TILE_ELEMS;
    #pragma unroll
    for (int mt = 0; mt < 2; mt++){
        int r0 = wm*32 + mt*16 + gid;
        #pragma unroll
        for (int nt = 0; nt < 8; nt++){
            int col = wn*64 + nt*8 + 2*tig;
            *(float2*)(dst + r0*D + col)     = make_float2(c[mt][nt][0], c[mt][nt][1]);
            *(float2*)(dst + (r0+8)*D + col) = make_float2(c[mt][nt][2], c[mt][nt][3]);
        }
    }
}

// ---------------- attention P·V style GEMM:  out[64,256] = A[64,64] * B[64,256] ----------------
// transA=0: A[m][k] = attm[m*PA + k]   (s_att: A = E, rscale = 1/rowsum)
// transA=1: A[m][k] = attm[k*PA + m]   (q_att: A = P_col^T, rscale = null)
__device__ __forceinline__ void attn_pv(const float* __restrict__ attm, int transA,
                                        const float* __restrict__ Btile,
                                        const float* __restrict__ rscale,
                                        float* __restrict__ out, int t){
    const int lane = t & 31, warp = t >> 5;
    const int gid = lane >> 2, tig = lane & 3;
    const int wm = warp >> 2, wn = warp & 3;
    float c[2][8][4];
    #pragma unroll
    for (int mt = 0; mt < 2; mt++)
        #pragma unroll
        for (int nt = 0; nt < 8; nt++)
            #pragma unroll
            for (int i = 0; i < 4; i++) c[mt][nt][i] = 0.f;

    for (int kb = 0; kb < 8; kb++){
        unsigned ah[2][4], al[2][4];
        #pragma unroll
        for (int mt = 0; mt < 2; mt++){
            int rbase = wm*32 + mt*16 + gid;
            #pragma unroll
            for (int p = 0; p < 4; p++){
                int rr = rbase + (p & 1)*8;
                int cc = kb*8 + tig + (p >> 1)*4;
                float v = transA ? attm[cc*PA + rr] : attm[rr*PA + cc];
                hilo(v, ah[mt][p], al[mt][p]);
            }
        }
        #pragma unroll
        for (int nt = 0; nt < 8; nt++){
            int d0 = wn*64 + nt*8 + gid;
            int k0 = kb*8 + tig;
            unsigned bh[2], bl[2];
            hilo(Btile[k0*PITCH + d0],       bh[0], bl[0]);
            hilo(Btile[(k0+4)*PITCH + d0],   bh[1], bl[1]);
            #pragma unroll
            for (int mt = 0; mt < 2; mt++){
                mma8(c[mt][nt], ah[mt], bh);
                mma8(c[mt][nt], ah[mt], bl);
                mma8(c[mt][nt], al[mt], bh);
            }
        }
    }
    #pragma unroll
    for (int mt = 0; mt < 2; mt++){
        int r0 = wm*32 + mt*16 + gid;
        float s0 = rscale ? rscale[r0]   : 1.0f;
        float s1 = rscale ? rscale[r0+8] : 1.0f;
        #pragma unroll
        for (int nt = 0; nt < 8; nt++){
            int col = wn*64 + nt*8 + 2*tig;
            out[r0*PITCH + col]       = c[mt][nt][0]*s0;
            out[r0*PITCH + col + 1]   = c[mt][nt][1]*s0;
            out[(r0+8)*PITCH + col]   = c[mt][nt][2]*s1;
            out[(r0+8)*PITCH + col+1] = c[mt][nt][3]*s1;
        }
    }
}

// ---------------- enhanced projection + mish + pool + LN (3xTF32 mma) ----------------
__device__ __forceinline__ void proj_phase(
    const float* __restrict__ xt, const float* __restrict__ at,
    const float* __restrict__ basep,
    float* pmax, float* psum, float* pool_out,
    const float* __restrict__ ln2g, const float* __restrict__ ln2b,
    float* red, int t)
{
    const int lane = t & 31, warp = t >> 5;
    const int gid = lane >> 2, tig = lane & 3;
    const int wm = warp >> 2, wn = warp & 3;

    float c[2][8][4];
    #pragma unroll
    for (int mt = 0; mt < 2; mt++){
        int r0 = wm*32 + mt*16 + gid;
        #pragma unroll
        for (int nt = 0; nt < 8; nt++){
            int col = wn*64 + nt*8 + 2*tig;
            float2 v0 = *(const float2*)(basep + r0*D + col);
            float2 v1 = *(const float2*)(basep + (r0+8)*D + col);
            c[mt][nt][0] = v0.x; c[mt][nt][1] = v0.y;
            c[mt][nt][2] = v1.x; c[mt][nt][3] = v1.y;
        }
    }

    for (int kb = 0; kb < 32; kb++){
        unsigned ah[2][3][4], al[2][3][4];
        #pragma unroll
        for (int mt = 0; mt < 2; mt++){
            int rbase = wm*32 + mt*16 + gid;
            #pragma unroll
            for (int p = 0; p < 4; p++){
                int rr = rbase + (p & 1)*8;
                int cc = kb*8 + tig + (p >> 1)*4;
                float x = xt[rr*PITCH + cc];
                float a = at[rr*PITCH + cc];
                hilo(a,           ah[mt][0][p], al[mt][0][p]);
                hilo(fabsf(x-a),  ah[mt][1][p], al[mt][1][p]);
                hilo(x*a,         ah[mt][2][p], al[mt][2][p]);
            }
        }
        #pragma unroll
        for (int nt = 0; nt < 8; nt++){
            #pragma unroll
            for (int w = 0; w < 3; w++){
                float4 wv = *(const float4*)(g_Wm + ((size_t)((kb*4 + w)*32 + wn*8 + nt))*128 + lane*4);
                unsigned bh[2] = { __float_as_uint(wv.x), __float_as_uint(wv.y) };
                unsigned bl[2] = { __float_as_uint(wv.z), __float_as_uint(wv.w) };
                #pragma unroll
                for (int mt = 0; mt < 2; mt++){
                    mma8(c[mt][nt], ah[mt][w], bh);
                    mma8(c[mt][nt], ah[mt][w], bl);
                    mma8(c[mt][nt], al[mt][w], bh);
                }
            }
        }
    }

    // mish + pooled max/sum per column j (own 16 cols: 8 nt x 2)
    float mymax[8][2], mysum[8][2];
    #pragma unroll
    for (int nt = 0; nt < 8; nt++){
        #pragma unroll
        for (int e = 0; e < 2; e++){
            float v00 = mishf(c[0][nt][e]);
            float v01 = mishf(c[0][nt][2+e]);
            float v10 = mishf(c[1][nt][e]);
            float v11 = mishf(c[1][nt][2+e]);
            float mx = fmaxf(fmaxf(v00, v01), fmaxf(v10, v11));
            float sm = (v00 + v01) + (v10 + v11);
            #pragma unroll
            for (int off = 4; off < 32; off <<= 1){
                mx = fmaxf(mx, __shfl_xor_sync(0xffffffffu, mx, off));
                sm += __shfl_xor_sync(0xffffffffu, sm, off);
            }
            mymax[nt][e] = mx; mysum[nt][e] = sm;
        }
    }
    if (wm == 1 && gid == 0){
        #pragma unroll
        for (int nt = 0; nt < 8; nt++)
            #pragma unroll
            for (int e = 0; e < 2; e++){
                int j = wn*64 + nt*8 + 2*tig + e;
                pmax[j] = mymax[nt][e]; psum[j] = mysum[nt][e];
            }
    }
    __syncthreads();
    if (wm == 0 && gid == 0){
        #pragma unroll
        for (int nt = 0; nt < 8; nt++)
            #pragma unroll
            for (int e = 0; e < 2; e++){
                int j = wn*64 + nt*8 + 2*tig + e;
                pool_out[j]     = fmaxf(mymax[nt][e], pmax[j]);
                pool_out[D + j] = (mysum[nt][e] + psum[j]) * (1.0f/(float)Lh);
            }
    }
    __syncthreads();

    // LayerNorm over 512
    float v0 = pool_out[t], v1 = pool_out[D + t];
    float S  = blockSum256(v0 + v1,       red, t);
    float SS = blockSum256(v0*v0 + v1*v1, red, t);
    float mean = S  * (1.0f/512.0f);
    float var  = SS * (1.0f/512.0f) - mean*mean;
    float inv  = rsqrtf(var + 1e-5f);
    pool_out[t]     = (v0 - mean)*inv*ln2g[t]     + ln2b[t];
    pool_out[D + t] = (v1 - mean)*inv*ln2g[D + t] + ln2b[D + t];
    __syncthreads();
}

// ---------------- kernel D: one CTA per (query, support) pair ----------------
__global__ void __launch_bounds__(256, 1) k_pair(
    const float* __restrict__ ln2g, const float* __restrict__ ln2b,
    const float* __restrict__ W2,  const float* __restrict__ b2,
    const float* __restrict__ W3,  const float* __restrict__ b3,
    const float* __restrict__ b1v)
{
    extern __shared__ float sm[];
    float* s_t  = sm + SM_S;
    float* q_t  = sm + SM_Q;
    float* a_t  = sm + SM_A;
    float* att  = sm + SM_ATT;
    float* pmax = sm + SM_PMAX;
    float* psum = sm + SM_PSUM;
    float* pool = sm + SM_POOL;
    float* rmax = sm + SM_RMAX;
    float* rsum = sm + SM_RSUM;
    float* cmax = sm + SM_CMAX;
    float* csum = sm + SM_CSUM;
    float* red  = sm + SM_RED;

    const int m = blockIdx.x;
    const int b = m / (NQh*Nh);
    const int rem = m % (NQh*Nh);
    const int iq = rem / Nh;
    const int n  = rem % Nh;
    const int sIdx = b*Nh + n;      // K = 1
    const int qIdx = b*NQh + iq;
    const int t = threadIdx.x;
    const int lane = t & 31, warp = t >> 5;
    const int gid = lane >> 2, tig = lane & 3;

    // load tiles into pitched smem
    {
        const float* sp = g_sN + (size_t)sIdx*TILE_ELEMS;
        const float* qp = g_qN + (size_t)qIdx*TILE_ELEMS;
        for (int idx = t; idx < TILE_ELEMS; idx += 256){
            int row = idx >> 8, col = idx & 255;
            s_t[row*PITCH + col] = sp[idx];
            q_t[row*PITCH + col] = qp[idx];
        }
    }
    __syncthreads();

    // att[l][k] = s[l] . q[k]  via 3xTF32 mma
    {
        const int wma = warp >> 1, wna = warp & 1;
        float ca[4][4];
        #pragma unroll
        for (int nt = 0; nt < 4; nt++)
            #pragma unroll
            for (int i = 0; i < 4; i++) ca[nt][i] = 0.f;
        for (int kb = 0; kb < 32; kb++){
            unsigned ah[4], al[4];
            #pragma unroll
            for (int p = 0; p < 4; p++){
                int rr = wma*16 + gid + (p & 1)*8;
                int cc = kb*8 + tig + (p >> 1)*4;
                hilo(s_t[rr*PITCH + cc], ah[p], al[p]);
            }
            #pragma unroll
            for (int nt = 0; nt < 4; nt++){
                int n0 = wna*32 + nt*8 + gid;
                unsigned bh[2], bl[2];
                hilo(q_t[n0*PITCH + kb*8 + tig],     bh[0], bl[0]);
                hilo(q_t[n0*PITCH + kb*8 + tig + 4], bh[1], bl[1]);
                mma8(ca[nt], ah, bh);
                mma8(ca[nt], ah, bl);
                mma8(ca[nt], al, bh);
            }
        }
        #pragma unroll
        for (int nt = 0; nt < 4; nt++){
            int r0 = wma*16 + gid;
            int col = wna*32 + nt*8 + 2*tig;
            att[r0*PA + col]       = ca[nt][0];
            att[r0*PA + col + 1]   = ca[nt][1];
            att[(r0+8)*PA + col]   = ca[nt][2];
            att[(r0+8)*PA + col+1] = ca[nt][3];
        }
    }
    __syncthreads();

    // row / column maxima
    if (t < 64){
        float mx = -3.4e38f;
        const float* row = att + t*PA;
        #pragma unroll 8
        for (int k2 = 0; k2 < 64; k2++) mx = fmaxf(mx, row[k2]);
        rmax[t] = mx;
    } else if (t < 128){
        int k = t - 64;
        float mx = -3.4e38f;
        for (int l = 0; l < 64; l++) mx = fmaxf(mx, att[l*PA + k]);
        cmax[k] = mx;
    }
    __syncthreads();

    // att := E = exp(att - rmax[l])
    {
        const int k = t & 63, l0 = t >> 6;
        #pragma unroll
        for (int i = 0; i < 16; i++){
            int l = l0 + 4*i;
            att[l*PA + k] = __expf(att[l*PA + k] - rmax[l]);
        }
    }
    __syncthreads();

    // row sums (reciprocal) and column sums (reciprocal, rebased to cmax)
    if (t < 64){
        float s = 0.f;
        const float* row = att + t*PA;
        #pragma unroll 8
        for (int k2 = 0; k2 < 64; k2++) s += row[k2];
        rsum[t] = 1.0f / s;
    } else if (t < 128){
        int k = t - 64;
        float cm = cmax[k];
        float s = 0.f;
        for (int l = 0; l < 64; l++){
            float h = __expf(0.5f*(rmax[l] - cm));
            s += att[l*PA + k] * h * h;
        }
        csum[k] = 1.0f / s;
    }
    __syncthreads();

    // s_att = (E @ Q) / rowsum  -> a_t
    attn_pv(att, 0, q_t, rsum, a_t, t);
    __syncthreads();

    // phase S -> pool[512..1023]
    proj_phase(s_t, a_t, g_base + (size_t)sIdx*TILE_ELEMS,
               pmax, psum, pool + 512, ln2g, ln2b, red, t);

    // att := P_col = exp(att_raw - cmax[k]) / colsum
    {
        const int k = t & 63, l0 = t >> 6;
        float ci = csum[k], cm = cmax[k];
        #pragma unroll
        for (int i = 0; i < 16; i++){
            int l = l0 + 4*i;
            float h = __expf(0.5f*(rmax[l] - cm));
            att[l*PA + k] = att[l*PA + k] * h * h * ci;
        }
    }
    __syncthreads();

    // q_att = P_col^T @ S -> a_t
    attn_pv(att, 1, s_t, (const float*)0, a_t, t);
    __syncthreads();

    // phase Q -> pool[0..511]
    proj_phase(q_t, a_t, g_base + (size_t)(NSUP + qIdx)*TILE_ELEMS,
               pmax, psum, pool, ln2g, ln2b, red, t);

    // MLP head
    {
        float accm = b1v[t];
        #pragma unroll 4
        for (int c = 0; c < 1024; c++)
            accm += pool[c] * g_W1T[c*D + t];
        float hv = mishf(accm);
        float part = hv * W2[t];
        float tot = blockSum256(part, red, t);
        if (t == 0){
            float h = tot + b2[0];
            g_logits[m] = mishf(h)*W3[0] + b3[0];
        }
    }
}

// ---------------- kernel E: min-append, logits layout, argmax ----------------
__global__ void k_final(float* __restrict__ out, int out_size){
    int u = threadIdx.x;
    if (u >= Bh*NQh) return;
    float v[Nh];
    float mn = 3.4e38f;
    #pragma unroll
    for (int n2 = 0; n2 < Nh; n2++){
        v[n2] = g_logits[u*Nh + n2];
        mn = fminf(mn, v[n2]);
    }
    if (out_size >= 1100){
        float best = -3.4e38f; int bi = 0;
        #pragma unroll
        for (int n2 = 0; n2 < Nh; n2++){
            out[u*(Nh+1) + n2] = v[n2];
            if (v[n2] > best){ best = v[n2]; bi = n2; }
        }
        out[u*(Nh+1) + Nh] = mn - 1.0f;
        if (out_size >= 1200) out[Bh*NQh*(Nh+1) + u] = (float)bi;
    } else if (out_size == Bh*NQh){
        float best = -3.4e38f; int bi = 0;
        #pragma unroll
        for (int n2 = 0; n2 < Nh; n2++)
            if (v[n2] > best){ best = v[n2]; bi = n2; }
        ((int*)out)[u] = bi;
    }
}

// ---------------- launch ----------------
extern "C" void kernel_launch(void* const* d_in, const int* in_sizes, int n_in,
                              void* d_out, int out_size)
{
    const float* support = (const float*)d_in[0];
    const float* query   = (const float*)d_in[1];
    const float* ln_g    = (const float*)d_in[2];
    const float* ln_b    = (const float*)d_in[3];
    const float* ln2_g   = (const float*)d_in[4];
    const float* ln2_b   = (const float*)d_in[5];
    const float* proj_W  = (const float*)d_in[6];
    const float* proj_b  = (const float*)d_in[7];
    const float* W1      = (const float*)d_in[8];
    const float* b1      = (const float*)d_in[9];
    const float* W2      = (const float*)d_in[10];
    const float* b2      = (const float*)d_in[11];
    const float* W3      = (const float*)d_in[12];
    const float* b3      = (const float*)d_in[13];

    cudaFuncSetAttribute(k_pair, cudaFuncAttributeMaxDynamicSharedMemorySize, SMEM_PAIR_BYTES);
    cudaFuncSetAttribute(k_base, cudaFuncAttributeMaxDynamicSharedMemorySize, SMEM_BASE_BYTES);

    k_ln<<<(NSUP + NQRY)*Lh, 256>>>(support, query, ln_g, ln_b);
    k_transposeW1<<<1024, 256>>>(W1);
    k_prepw<<<512, 256>>>(proj_W);
    k_base<<<NTILE, 256, SMEM_BASE_BYTES>>>(proj_b);
    k_pair<<<Mh, 256, SMEM_PAIR_BYTES>>>(ln2_g, ln2_b, W2, b2, W3, b3, b1);
    k_final<<<1, 128>>>((float*)d_out, out_size);
}

// round 3
// speedup vs baseline: 2.9462x; 1.4428x over previous
#include <cuda_runtime.h>
#include <cstdint>

#define D 256
#define Lh 64
#define Bh 2
#define Nh 10
#define NQh 50
#define Mh 1000
#define NSUP 20
#define NQRY 100
#define NTILE 120
#define PITCH 260
#define PA 68
#define TILE_ELEMS (Lh*D)

// ---------------- scratch (device globals; no allocations allowed) ----------------
__device__ float g_sN[NSUP*TILE_ELEMS];
__device__ float g_qN[NQRY*TILE_ELEMS];
__device__ float g_W1T[4*D*D];                    // W1 transposed (for MLP head)
__device__ float4 g_Wm4[16*4*32*32];              // proj_W bf16 hi/lo b-fragments (1MB)
__device__ float4 g_base4[NTILE*16*8*32];         // base = x@W0^T + b, fragment-native (7.9MB)
__device__ float g_logits[Mh];

// Shared-memory layout (floats) for the pair kernel
#define SM_S    0
#define SM_Q    (SM_S + Lh*PITCH)
#define SM_A    (SM_Q + Lh*PITCH)
#define SM_ATT  (SM_A + Lh*PITCH)
#define SM_PMAX (SM_ATT + Lh*PA)
#define SM_PSUM (SM_PMAX + D)
#define SM_POOL (SM_PSUM + D)       // 1024: [0..511]=q_pool, [512..1023]=s_pool
#define SM_RMAX (SM_POOL + 1024)
#define SM_RSUM (SM_RMAX + 64)
#define SM_CMAX (SM_RSUM + 64)
#define SM_CSUM (SM_CMAX + 64)
#define SM_RED  (SM_CSUM + 64)
#define SM_TOTAL (SM_RED + 32)
#define SMEM_PAIR_BYTES (SM_TOTAL*4)
#define SMEM_BASE_BYTES (Lh*PITCH*4)

// ---------------- bf16 split helpers ----------------
// pack2(x0,x1): low 16 bits = bf16(x0), high = bf16(x1)  (k, k+1 order for mma)
__device__ __forceinline__ unsigned pack2(float x0, float x1){
    unsigned r; asm("cvt.rn.bf16x2.f32 %0, %1, %2;" : "=r"(r) : "f"(x1), "f"(x0)); return r;
}
__device__ __forceinline__ void split2(float x0, float x1, unsigned &h, unsigned &l){
    h = pack2(x0, x1);
    float h0 = __uint_as_float(h << 16);
    float h1 = __uint_as_float(h & 0xffff0000u);
    l = pack2(x0 - h0, x1 - h1);
}
__device__ __forceinline__ void mmab(float* c, const unsigned* a, const unsigned* b){
    asm volatile("mma.sync.aligned.m16n8k16.row.col.f32.bf16.bf16.f32 "
        "{%0,%1,%2,%3}, {%4,%5,%6,%7}, {%8,%9}, {%0,%1,%2,%3};\n"
        : "+f"(c[0]), "+f"(c[1]), "+f"(c[2]), "+f"(c[3])
        : "r"(a[0]), "r"(a[1]), "r"(a[2]), "r"(a[3]), "r"(b[0]), "r"(b[1]));
}
__device__ __forceinline__ void mma3(float* c, const unsigned* ah, const unsigned* al,
                                     const unsigned* bh, const unsigned* bl){
    mmab(c, ah, bh); mmab(c, ah, bl); mmab(c, al, bh);
}

// mish(x) = x * tanh(softplus(x)) = x * (u^2+2u)/(u^2+2u+2), u = e^x
__device__ __forceinline__ float mishf(float x){
    if (x > 20.0f) return x;
    float u = __expf(x);
    float v = u*u + 2.0f*u;
    return x * v / (v + 2.0f);
}

__device__ __forceinline__ float blockSum256(float v, float* red, int t){
    #pragma unroll
    for (int o = 16; o > 0; o >>= 1) v += __shfl_xor_sync(0xffffffffu, v, o);
    if ((t & 31) == 0) red[t >> 5] = v;
    __syncthreads();
    float s = red[0]+red[1]+red[2]+red[3]+red[4]+red[5]+red[6]+red[7];
    __syncthreads();
    return s;
}

// ---------------- kernel A: row LayerNorm of support & query ----------------
__global__ void k_ln(const float* __restrict__ sup, const float* __restrict__ qry,
                     const float* __restrict__ gg, const float* __restrict__ bb){
    __shared__ float rs[8], rq[8];
    int r = blockIdx.x, t = threadIdx.x;
    const float* src; float* dst;
    const int nsr = NSUP*Lh;
    if (r < nsr){ src = sup + (size_t)r*D; dst = g_sN + (size_t)r*D; }
    else        { src = qry + (size_t)(r-nsr)*D; dst = g_qN + (size_t)(r-nsr)*D; }
    float x = src[t];
    float s = x, q = x*x;
    #pragma unroll
    for (int o = 16; o > 0; o >>= 1){
        s += __shfl_xor_sync(0xffffffffu, s, o);
        q += __shfl_xor_sync(0xffffffffu, q, o);
    }
    if ((t & 31) == 0){ rs[t>>5] = s; rq[t>>5] = q; }
    __syncthreads();
    float S = 0.f, Q2 = 0.f;
    #pragma unroll
    for (int w = 0; w < 8; w++){ S += rs[w]; Q2 += rq[w]; }
    float mu  = S  * (1.0f/D);
    float var = Q2 * (1.0f/D) - mu*mu;
    float inv = rsqrtf(var + 1e-5f);
    dst[t] = (x - mu)*inv*gg[t] + bb[t];
}

// ---------------- kernel B: transpose W1 [256][1024] -> [1024][256] ----------------
__global__ void k_transposeW1(const float* __restrict__ W){
    int c = blockIdx.x, j = threadIdx.x;
    g_W1T[c*D + j] = W[(size_t)j*1024 + c];
}

// ---------------- kernel B2: proj_W -> bf16 hi/lo b-fragments ----------------
// idx bits: lane[0:5) jt[5:10) w[10:12) kb[12:16)
// w = 0,1,2 -> weight blocks (input cols 256..511, 512..767, 768..1023); w = 3 -> block 0 (base)
__global__ void k_prepw(const float* __restrict__ pw){
    int idx = blockIdx.x*256 + threadIdx.x;     // 65536 total
    int lane = idx & 31;
    int jt   = (idx >> 5) & 31;
    int w    = (idx >> 10) & 3;
    int kb   = idx >> 12;
    int tig = lane & 3, gid = lane >> 2;
    int j = jt*8 + gid;
    int cblk = (w == 3) ? 0 : (w + 1);
    size_t base = (size_t)j*1024 + cblk*256 + kb*16 + 2*tig;
    unsigned bh0, bl0, bh1, bl1;
    split2(pw[base],     pw[base + 1], bh0, bl0);
    split2(pw[base + 8], pw[base + 9], bh1, bl1);
    g_Wm4[idx] = make_float4(__uint_as_float(bh0), __uint_as_float(bh1),
                             __uint_as_float(bl0), __uint_as_float(bl1));
}

// ---------------- kernel C: per-tile base = x @ W0^T + proj_b  (bf16 3-term mma) ----------------
__global__ void __launch_bounds__(256,1) k_base(const float* __restrict__ pb){
    extern __shared__ float smx[];
    int tile = blockIdx.x, t = threadIdx.x;
    const float* src = (tile < NSUP) ? (g_sN + (size_t)tile*TILE_ELEMS)
                                     : (g_qN + (size_t)(tile-NSUP)*TILE_ELEMS);
    for (int idx = t; idx < TILE_ELEMS; idx += 256){
        int row = idx >> 8, col = idx & 255;
        smx[row*PITCH + col] = src[idx];
    }
    __syncthreads();

    const int lane = t & 31, warp = t >> 5;
    const int gid = lane >> 2, tig = lane & 3;
    const int wm = warp >> 2, wn = warp & 3;

    float c[2][8][4];
    #pragma unroll
    for (int nt = 0; nt < 8; nt++){
        int col = wn*64 + nt*8 + 2*tig;
        float b0 = pb[col], b1 = pb[col+1];
        #pragma unroll
        for (int mt = 0; mt < 2; mt++){
            c[mt][nt][0] = b0; c[mt][nt][1] = b1;
            c[mt][nt][2] = b0; c[mt][nt][3] = b1;
        }
    }
    for (int kb = 0; kb < 16; kb++){
        unsigned ah[2][4], al[2][4];
        #pragma unroll
        for (int mt = 0; mt < 2; mt++){
            int r0 = wm*32 + mt*16 + gid;
            int c0 = kb*16 + 2*tig;
            #pragma unroll
            for (int p = 0; p < 4; p++){
                float2 x2 = *(const float2*)(smx + (r0 + (p & 1)*8)*PITCH + c0 + (p >> 1)*8);
                split2(x2.x, x2.y, ah[mt][p], al[mt][p]);
            }
        }
        #pragma unroll
        for (int nt = 0; nt < 8; nt++){
            float4 wv = __ldg(&g_Wm4[((kb*4 + 3)*32 + wn*8 + nt)*32 + lane]);
            unsigned bh[2] = { __float_as_uint(wv.x), __float_as_uint(wv.y) };
            unsigned bl[2] = { __float_as_uint(wv.z), __float_as_uint(wv.w) };
            mma3(c[0][nt], ah[0], al[0], bh, bl);
            mma3(c[1][nt], ah[1], al[1], bh, bl);
        }
    }
    #pragma unroll
    for (int mt = 0; mt < 2; mt++)
        #pragma unroll
        for (int nt = 0; nt < 8; nt++)
            g_base4[((tile*16 + warp*2 + mt)*8 + nt)*32 + lane] =
                make_float4(c[mt][nt][0], c[mt][nt][1], c[mt][nt][2], c[mt][nt][3]);
}

// ---------------- attention P·V GEMM: out[64,256] = A[64,64] * B[64,256] (bf16 3-term) ------
// transA=0: A[m][k] = attm[m*PA + k]   (s_att: A = E, rscale = 1/rowsum)
// transA=1: A[m][k] = attm[k*PA + m]   (q_att: A = P_col^T, rscale = null)
__device__ __forceinline__ void attn_pv(const float* __restrict__ attm, int transA,
                                        const float* __restrict__ Btile,
                                        const float* __restrict__ rscale,
                                        float* __restrict__ out, int t){
    const int lane = t & 31, warp = t >> 5;
    const int gid = lane >> 2, tig = lane & 3;
    const int wm = warp >> 2, wn = warp & 3;
    float c[2][8][4];
    #pragma unroll
    for (int mt = 0; mt < 2; mt++)
        #pragma unroll
        for (int nt = 0; nt < 8; nt++)
            #pragma unroll
            for (int i = 0; i < 4; i++) c[mt][nt][i] = 0.f;

    for (int kb = 0; kb < 4; kb++){
        unsigned ah[2][4], al[2][4];
        #pragma unroll
        for (int mt = 0; mt < 2; mt++){
            int r0 = wm*32 + mt*16 + gid;
            int c0 = kb*16 + 2*tig;
            #pragma unroll
            for (int p = 0; p < 4; p++){
                int rr = r0 + (p & 1)*8;
                int cc = c0 + (p >> 1)*8;
                float v0, v1;
                if (transA){ v0 = attm[cc*PA + rr]; v1 = attm[(cc+1)*PA + rr]; }
                else { float2 v = *(const float2*)(attm + rr*PA + cc); v0 = v.x; v1 = v.y; }
                split2(v0, v1, ah[mt][p], al[mt][p]);
            }
        }
        #pragma unroll
        for (int nt = 0; nt < 8; nt++){
            int d0 = wn*64 + nt*8 + gid;
            int k0 = kb*16 + 2*tig;
            unsigned bh[2], bl[2];
            split2(Btile[k0*PITCH + d0],     Btile[(k0+1)*PITCH + d0], bh[0], bl[0]);
            split2(Btile[(k0+8)*PITCH + d0], Btile[(k0+9)*PITCH + d0], bh[1], bl[1]);
            mma3(c[0][nt], ah[0], al[0], bh, bl);
            mma3(c[1][nt], ah[1], al[1], bh, bl);
        }
    }
    #pragma unroll
    for (int mt = 0; mt < 2; mt++){
        int r0 = wm*32 + mt*16 + gid;
        float s0 = rscale ? rscale[r0]   : 1.0f;
        float s1 = rscale ? rscale[r0+8] : 1.0f;
        #pragma unroll
        for (int nt = 0; nt < 8; nt++){
            int col = wn*64 + nt*8 + 2*tig;
            *(float2*)(out + r0*PITCH + col)     = make_float2(c[mt][nt][0]*s0, c[mt][nt][1]*s0);
            *(float2*)(out + (r0+8)*PITCH + col) = make_float2(c[mt][nt][2]*s1, c[mt][nt][3]*s1);
        }
    }
}

// ---------------- enhanced projection + mish + pool + LN (bf16 3-term mma) ----------------
__device__ __forceinline__ void proj_phase(
    const float* __restrict__ xt, const float* __restrict__ at,
    const float4* __restrict__ basef,
    float* pmax, float* psum, float* pool_out,
    const float* __restrict__ ln2g, const float* __restrict__ ln2b,
    float* red, int t)
{
    const int lane = t & 31, warp = t >> 5;
    const int gid = lane >> 2, tig = lane & 3;
    const int wm = warp >> 2, wn = warp & 3;

    float c[2][8][4];
    #pragma unroll
    for (int mt = 0; mt < 2; mt++)
        #pragma unroll
        for (int nt = 0; nt < 8; nt++){
            float4 v = __ldg(&basef[((warp*2 + mt)*8 + nt)*32 + lane]);
            c[mt][nt][0] = v.x; c[mt][nt][1] = v.y; c[mt][nt][2] = v.z; c[mt][nt][3] = v.w;
        }

    for (int kb = 0; kb < 16; kb++){
        unsigned ah[2][3][4], al[2][3][4];
        #pragma unroll
        for (int mt = 0; mt < 2; mt++){
            int r0 = wm*32 + mt*16 + gid;
            int c0 = kb*16 + 2*tig;
            #pragma unroll
            for (int p = 0; p < 4; p++){
                int rr = r0 + (p & 1)*8;
                int cc = c0 + (p >> 1)*8;
                float2 x2 = *(const float2*)(xt + rr*PITCH + cc);
                float2 a2 = *(const float2*)(at + rr*PITCH + cc);
                split2(a2.x, a2.y, ah[mt][0][p], al[mt][0][p]);
                split2(fabsf(x2.x - a2.x), fabsf(x2.y - a2.y), ah[mt][1][p], al[mt][1][p]);
                split2(x2.x*a2.x, x2.y*a2.y, ah[mt][2][p], al[mt][2][p]);
            }
        }
        #pragma unroll
        for (int nt = 0; nt < 8; nt++){
            #pragma unroll
            for (int w = 0; w < 3; w++){
                float4 wv = __ldg(&g_Wm4[((kb*4 + w)*32 + wn*8 + nt)*32 + lane]);
                unsigned bh[2] = { __float_as_uint(wv.x), __float_as_uint(wv.y) };
                unsigned bl[2] = { __float_as_uint(wv.z), __float_as_uint(wv.w) };
                mma3(c[0][nt], ah[0][w], al[0][w], bh, bl);
                mma3(c[1][nt], ah[1][w], al[1][w], bh, bl);
            }
        }
    }

    // mish + pooled max/sum per column j (warp owns 64 cols; reduce over gid via shuffles)
    float mymax[8][2], mysum[8][2];
    #pragma unroll
    for (int nt = 0; nt < 8; nt++){
        #pragma unroll
        for (int e = 0; e < 2; e++){
            float v00 = mishf(c[0][nt][e]);
            float v01 = mishf(c[0][nt][2+e]);
            float v10 = mishf(c[1][nt][e]);
            float v11 = mishf(c[1][nt][2+e]);
            float mx = fmaxf(fmaxf(v00, v01), fmaxf(v10, v11));
            float sm = (v00 + v01) + (v10 + v11);
            #pragma unroll
            for (int off = 4; off < 32; off <<= 1){
                mx = fmaxf(mx, __shfl_xor_sync(0xffffffffu, mx, off));
                sm += __shfl_xor_sync(0xffffffffu, sm, off);
            }
            mymax[nt][e] = mx; mysum[nt][e] = sm;
        }
    }
    if (wm == 1 && gid == 0){
        #pragma unroll
        for (int nt = 0; nt < 8; nt++)
            #pragma unroll
            for (int e = 0; e < 2; e++){
                int j = wn*64 + nt*8 + 2*tig + e;
                pmax[j] = mymax[nt][e]; psum[j] = mysum[nt][e];
            }
    }
    __syncthreads();
    if (wm == 0 && gid == 0){
        #pragma unroll
        for (int nt = 0; nt < 8; nt++)
            #pragma unroll
            for (int e = 0; e < 2; e++){
                int j = wn*64 + nt*8 + 2*tig + e;
                pool_out[j]     = fmaxf(mymax[nt][e], pmax[j]);
                pool_out[D + j] = (mysum[nt][e] + psum[j]) * (1.0f/(float)Lh);
            }
    }
    __syncthreads();

    // LayerNorm over 512
    float v0 = pool_out[t], v1 = pool_out[D + t];
    float S  = blockSum256(v0 + v1,       red, t);
    float SS = blockSum256(v0*v0 + v1*v1, red, t);
    float mean = S  * (1.0f/512.0f);
    float var  = SS * (1.0f/512.0f) - mean*mean;
    float inv  = rsqrtf(var + 1e-5f);
    pool_out[t]     = (v0 - mean)*inv*ln2g[t]     + ln2b[t];
    pool_out[D + t] = (v1 - mean)*inv*ln2g[D + t] + ln2b[D + t];
    __syncthreads();
}

// ---------------- kernel D: one CTA per (query, support) pair ----------------
__global__ void __launch_bounds__(256, 1) k_pair(
    const float* __restrict__ ln2g, const float* __restrict__ ln2b,
    const float* __restrict__ W2,  const float* __restrict__ b2,
    const float* __restrict__ W3,  const float* __restrict__ b3,
    const float* __restrict__ b1v)
{
    extern __shared__ float sm[];
    float* s_t  = sm + SM_S;
    float* q_t  = sm + SM_Q;
    float* a_t  = sm + SM_A;
    float* att  = sm + SM_ATT;
    float* pmax = sm + SM_PMAX;
    float* psum = sm + SM_PSUM;
    float* pool = sm + SM_POOL;
    float* rmax = sm + SM_RMAX;
    float* rsum = sm + SM_RSUM;
    float* cmax = sm + SM_CMAX;
    float* csum = sm + SM_CSUM;
    float* red  = sm + SM_RED;

    const int m = blockIdx.x;
    const int b = m / (NQh*Nh);
    const int rem = m % (NQh*Nh);
    const int iq = rem / Nh;
    const int n  = rem % Nh;
    const int sIdx = b*Nh + n;      // K = 1
    const int qIdx = b*NQh + iq;
    const int t = threadIdx.x;
    const int lane = t & 31, warp = t >> 5;
    const int gid = lane >> 2, tig = lane & 3;

    // load tiles into pitched smem
    {
        const float* sp = g_sN + (size_t)sIdx*TILE_ELEMS;
        const float* qp = g_qN + (size_t)qIdx*TILE_ELEMS;
        for (int idx = t; idx < TILE_ELEMS; idx += 256){
            int row = idx >> 8, col = idx & 255;
            s_t[row*PITCH + col] = sp[idx];
            q_t[row*PITCH + col] = qp[idx];
        }
    }
    __syncthreads();

    // att[l][k] = s[l] . q[k]  via bf16 3-term mma
    {
        const int wma = warp >> 1, wna = warp & 1;
        float ca[4][4];
        #pragma unroll
        for (int nt = 0; nt < 4; nt++)
            #pragma unroll
            for (int i = 0; i < 4; i++) ca[nt][i] = 0.f;
        for (int kb = 0; kb < 16; kb++){
            unsigned ah[4], al[4];
            int r0 = wma*16 + gid;
            int c0 = kb*16 + 2*tig;
            #pragma unroll
            for (int p = 0; p < 4; p++){
                float2 s2 = *(const float2*)(s_t + (r0 + (p & 1)*8)*PITCH + c0 + (p >> 1)*8);
                split2(s2.x, s2.y, ah[p], al[p]);
            }
            #pragma unroll
            for (int nt = 0; nt < 4; nt++){
                int n0 = wna*32 + nt*8 + gid;
                unsigned bh[2], bl[2];
                float2 q0 = *(const float2*)(q_t + n0*PITCH + c0);
                float2 q1 = *(const float2*)(q_t + n0*PITCH + c0 + 8);
                split2(q0.x, q0.y, bh[0], bl[0]);
                split2(q1.x, q1.y, bh[1], bl[1]);
                mma3(ca[nt], ah, al, bh, bl);
            }
        }
        #pragma unroll
        for (int nt = 0; nt < 4; nt++){
            int r0 = wma*16 + gid;
            int col = wna*32 + nt*8 + 2*tig;
            *(float2*)(att + r0*PA + col)     = make_float2(ca[nt][0], ca[nt][1]);
            *(float2*)(att + (r0+8)*PA + col) = make_float2(ca[nt][2], ca[nt][3]);
        }
    }
    __syncthreads();

    // row / column maxima
    if (t < 64){
        float mx = -3.4e38f;
        const float* row = att + t*PA;
        #pragma unroll 8
        for (int k2 = 0; k2 < 64; k2++) mx = fmaxf(mx, row[k2]);
        rmax[t] = mx;
    } else if (t < 128){
        int k = t - 64;
        float mx = -3.4e38f;
        for (int l = 0; l < 64; l++) mx = fmaxf(mx, att[l*PA + k]);
        cmax[k] = mx;
    }
    __syncthreads();

    // att := E = exp(att - rmax[l])
    {
        const int k = t & 63, l0 = t >> 6;
        #pragma unroll
        for (int i = 0; i < 16; i++){
            int l = l0 + 4*i;
            att[l*PA + k] = __expf(att[l*PA + k] - rmax[l]);
        }
    }
    __syncthreads();

    // row sums (reciprocal) and column sums (reciprocal, rebased to cmax)
    if (t < 64){
        float s = 0.f;
        const float* row = att + t*PA;
        #pragma unroll 8
        for (int k2 = 0; k2 < 64; k2++) s += row[k2];
        rsum[t] = 1.0f / s;
    } else if (t < 128){
        int k = t - 64;
        float cm = cmax[k];
        float s = 0.f;
        for (int l = 0; l < 64; l++){
            float h = __expf(0.5f*(rmax[l] - cm));   // split to avoid overflow
            s += att[l*PA + k] * h * h;
        }
        csum[k] = 1.0f / s;
    }
    __syncthreads();

    // s_att = (E @ Q) / rowsum  -> a_t
    attn_pv(att, 0, q_t, rsum, a_t, t);
    __syncthreads();

    // phase S -> pool[512..1023]
    proj_phase(s_t, a_t, g_base4 + (size_t)sIdx*4096,
               pmax, psum, pool + 512, ln2g, ln2b, red, t);

    // att := P_col = exp(att_raw - cmax[k]) / colsum
    {
        const int k = t & 63, l0 = t >> 6;
        float ci = csum[k], cm = cmax[k];
        #pragma unroll
        for (int i = 0; i < 16; i++){
            int l = l0 + 4*i;
            float h = __expf(0.5f*(rmax[l] - cm));
            att[l*PA + k] = att[l*PA + k] * h * h * ci;
        }
    }
    __syncthreads();

    // q_att = P_col^T @ S -> a_t
    attn_pv(att, 1, s_t, (const float*)0, a_t, t);
    __syncthreads();

    // phase Q -> pool[0..511]
    proj_phase(q_t, a_t, g_base4 + (size_t)(NSUP + qIdx)*4096,
               pmax, psum, pool, ln2g, ln2b, red, t);

    // MLP head: cat = [q_pool | s_pool] (1024); h1 = mish(cat @ W1^T + b1)
    {
        float accm = b1v[t];
        #pragma unroll 4
        for (int c = 0; c < 1024; c++)
            accm += pool[c] * g_W1T[c*D + t];
        float hv = mishf(accm);
        float part = hv * W2[t];
        float tot = blockSum256(part, red, t);
        if (t == 0){
            float h = tot + b2[0];
            g_logits[m] = mishf(h)*W3[0] + b3[0];
        }
    }
}

// ---------------- kernel E: min-append, logits layout, argmax ----------------
__global__ void k_final(float* __restrict__ out, int out_size){
    int u = threadIdx.x;
    if (u >= Bh*NQh) return;
    float v[Nh];
    float mn = 3.4e38f;
    #pragma unroll
    for (int n2 = 0; n2 < Nh; n2++){
        v[n2] = g_logits[u*Nh + n2];
        mn = fminf(mn, v[n2]);
    }
    if (out_size >= 1100){
        float best = -3.4e38f; int bi = 0;
        #pragma unroll
        for (int n2 = 0; n2 < Nh; n2++){
            out[u*(Nh+1) + n2] = v[n2];
            if (v[n2] > best){ best = v[n2]; bi = n2; }
        }
        out[u*(Nh+1) + Nh] = mn - 1.0f;
        if (out_size >= 1200) out[Bh*NQh*(Nh+1) + u] = (float)bi;
    } else if (out_size == Bh*NQh){
        float best = -3.4e38f; int bi = 0;
        #pragma unroll
        for (int n2 = 0; n2 < Nh; n2++)
            if (v[n2] > best){ best = v[n2]; bi = n2; }
        ((int*)out)[u] = bi;
    }
}

// ---------------- launch ----------------
extern "C" void kernel_launch(void* const* d_in, const int* in_sizes, int n_in,
                              void* d_out, int out_size)
{
    const float* support = (const float*)d_in[0];
    const float* query   = (const float*)d_in[1];
    const float* ln_g    = (const float*)d_in[2];
    const float* ln_b    = (const float*)d_in[3];
    const float* ln2_g   = (const float*)d_in[4];
    const float* ln2_b   = (const float*)d_in[5];
    const float* proj_W  = (const float*)d_in[6];
    const float* proj_b  = (const float*)d_in[7];
    const float* W1      = (const float*)d_in[8];
    const float* b1      = (const float*)d_in[9];
    const float* W2      = (const float*)d_in[10];
    const float* b2      = (const float*)d_in[11];
    const float* W3      = (const float*)d_in[12];
    const float* b3      = (const float*)d_in[13];

    cudaFuncSetAttribute(k_pair, cudaFuncAttributeMaxDynamicSharedMemorySize, SMEM_PAIR_BYTES);
    cudaFuncSetAttribute(k_base, cudaFuncAttributeMaxDynamicSharedMemorySize, SMEM_BASE_BYTES);

    k_ln<<<(NSUP + NQRY)*Lh, 256>>>(support, query, ln_g, ln_b);
    k_transposeW1<<<1024, 256>>>(W1);
    k_prepw<<<256, 256>>>(proj_W);
    k_base<<<NTILE, 256, SMEM_BASE_BYTES>>>(proj_b);
    k_pair<<<Mh, 256, SMEM_PAIR_BYTES>>>(ln2_g, ln2_b, W2, b2, W3, b3, b1);
    k_final<<<1, 128>>>((float*)d_out, out_size);
}

// round 4
// speedup vs baseline: 3.4783x; 1.1806x over previous
#include <cuda_runtime.h>
#include <cstdint>

#define D 256
#define Lh 64
#define Bh 2
#define Nh 10
#define NQh 50
#define Mh 1000
#define NSUP 20
#define NQRY 100
#define NTILE 120
#define PITCH 260
#define PA 68
#define TILE_ELEMS (Lh*D)

// ---------------- scratch (device globals; no allocations allowed) ----------------
__device__ float g_sN[NSUP*TILE_ELEMS];
__device__ float g_qN[NQRY*TILE_ELEMS];
__device__ float g_W1T[4*D*D];                    // W1 transposed (for MLP head)
__device__ float4 g_Wm4[16*4*32*32];              // proj_W bf16 hi/lo b-fragments (1MB)
__device__ float4 g_base4[NTILE*16*8*32];         // base = x@W0^T + b, fragment-native
__device__ float g_logits[Mh];

// Shared-memory layout (floats) for the pair kernel
#define SM_S    0
#define SM_Q    (SM_S + Lh*PITCH)
#define SM_A    (SM_Q + Lh*PITCH)
#define SM_ATT  (SM_A + Lh*PITCH)
#define SM_PMAX (SM_ATT + Lh*PA)
#define SM_PSUM (SM_PMAX + D)
#define SM_POOL (SM_PSUM + D)       // 1024: [0..511]=q_pool, [512..1023]=s_pool
#define SM_RMAX (SM_POOL + 1024)
#define SM_RSUM (SM_RMAX + 64)
#define SM_CMAX (SM_RSUM + 64)
#define SM_CSUM (SM_CMAX + 64)
#define SM_RED  (SM_CSUM + 64)
#define SM_TOTAL (SM_RED + 32)
#define SMEM_PAIR_BYTES (SM_TOTAL*4)
#define SMEM_BASE_BYTES (Lh*PITCH*4)

// ---------------- bf16 split helpers ----------------
__device__ __forceinline__ unsigned pack2(float x0, float x1){
    unsigned r; asm("cvt.rn.bf16x2.f32 %0, %1, %2;" : "=r"(r) : "f"(x1), "f"(x0)); return r;
}
__device__ __forceinline__ void split2(float x0, float x1, unsigned &h, unsigned &l){
    h = pack2(x0, x1);
    float h0 = __uint_as_float(h << 16);
    float h1 = __uint_as_float(h & 0xffff0000u);
    l = pack2(x0 - h0, x1 - h1);
}
__device__ __forceinline__ void mmab(float* c, const unsigned* a, const unsigned* b){
    asm volatile("mma.sync.aligned.m16n8k16.row.col.f32.bf16.bf16.f32 "
        "{%0,%1,%2,%3}, {%4,%5,%6,%7}, {%8,%9}, {%0,%1,%2,%3};\n"
        : "+f"(c[0]), "+f"(c[1]), "+f"(c[2]), "+f"(c[3])
        : "r"(a[0]), "r"(a[1]), "r"(a[2]), "r"(a[3]), "r"(b[0]), "r"(b[1]));
}
__device__ __forceinline__ void mma3(float* c, const unsigned* ah, const unsigned* al,
                                     const unsigned* bh, const unsigned* bl){
    mmab(c, ah, bh); mmab(c, ah, bl); mmab(c, al, bh);
}

// mish(x) = x * tanh(softplus(x)) = x * (u^2+2u)/(u^2+2u+2), u = e^x
__device__ __forceinline__ float mishf(float x){
    if (x > 20.0f) return x;
    float u = __expf(x);
    float v = u*u + 2.0f*u;
    return x * v / (v + 2.0f);
}

// block-wide sum over 512 threads (16 warps)
__device__ __forceinline__ float blockSum512(float v, float* red, int t){
    #pragma unroll
    for (int o = 16; o > 0; o >>= 1) v += __shfl_xor_sync(0xffffffffu, v, o);
    if ((t & 31) == 0) red[t >> 5] = v;
    __syncthreads();
    float s = 0.f;
    #pragma unroll
    for (int w = 0; w < 16; w++) s += red[w];
    __syncthreads();
    return s;
}

// ---------------- kernel A: row LayerNorm of support & query ----------------
__global__ void k_ln(const float* __restrict__ sup, const float* __restrict__ qry,
                     const float* __restrict__ gg, const float* __restrict__ bb){
    __shared__ float rs[8], rq[8];
    int r = blockIdx.x, t = threadIdx.x;
    const float* src; float* dst;
    const int nsr = NSUP*Lh;
    if (r < nsr){ src = sup + (size_t)r*D; dst = g_sN + (size_t)r*D; }
    else        { src = qry + (size_t)(r-nsr)*D; dst = g_qN + (size_t)(r-nsr)*D; }
    float x = src[t];
    float s = x, q = x*x;
    #pragma unroll
    for (int o = 16; o > 0; o >>= 1){
        s += __shfl_xor_sync(0xffffffffu, s, o);
        q += __shfl_xor_sync(0xffffffffu, q, o);
    }
    if ((t & 31) == 0){ rs[t>>5] = s; rq[t>>5] = q; }
    __syncthreads();
    float S = 0.f, Q2 = 0.f;
    #pragma unroll
    for (int w = 0; w < 8; w++){ S += rs[w]; Q2 += rq[w]; }
    float mu  = S  * (1.0f/D);
    float var = Q2 * (1.0f/D) - mu*mu;
    float inv = rsqrtf(var + 1e-5f);
    dst[t] = (x - mu)*inv*gg[t] + bb[t];
}

// ---------------- kernel B: transpose W1 [256][1024] -> [1024][256] ----------------
__global__ void k_transposeW1(const float* __restrict__ W){
    int c = blockIdx.x, j = threadIdx.x;
    g_W1T[c*D + j] = W[(size_t)j*1024 + c];
}

// ---------------- kernel B2: proj_W -> bf16 hi/lo b-fragments ----------------
__global__ void k_prepw(const float* __restrict__ pw){
    int idx = blockIdx.x*256 + threadIdx.x;     // 65536 total
    int lane = idx & 31;
    int jt   = (idx >> 5) & 31;
    int w    = (idx >> 10) & 3;
    int kb   = idx >> 12;
    int tig = lane & 3, gid = lane >> 2;
    int j = jt*8 + gid;
    int cblk = (w == 3) ? 0 : (w + 1);
    size_t base = (size_t)j*1024 + cblk*256 + kb*16 + 2*tig;
    unsigned bh0, bl0, bh1, bl1;
    split2(pw[base],     pw[base + 1], bh0, bl0);
    split2(pw[base + 8], pw[base + 9], bh1, bl1);
    g_Wm4[idx] = make_float4(__uint_as_float(bh0), __uint_as_float(bh1),
                             __uint_as_float(bl0), __uint_as_float(bl1));
}

// ---------------- kernel C: per-tile base = x @ W0^T + proj_b ----------------
__global__ void __launch_bounds__(256,1) k_base(const float* __restrict__ pb){
    extern __shared__ float smx[];
    int tile = blockIdx.x, t = threadIdx.x;
    const float* src = (tile < NSUP) ? (g_sN + (size_t)tile*TILE_ELEMS)
                                     : (g_qN + (size_t)(tile-NSUP)*TILE_ELEMS);
    for (int idx = t; idx < TILE_ELEMS; idx += 256){
        int row = idx >> 8, col = idx & 255;
        smx[row*PITCH + col] = src[idx];
    }
    __syncthreads();

    const int lane = t & 31, warp = t >> 5;
    const int gid = lane >> 2, tig = lane & 3;
    const int wm = warp >> 2, wn = warp & 3;

    float c[2][8][4];
    #pragma unroll
    for (int nt = 0; nt < 8; nt++){
        int col = wn*64 + nt*8 + 2*tig;
        float b0 = pb[col], b1 = pb[col+1];
        #pragma unroll
        for (int mt = 0; mt < 2; mt++){
            c[mt][nt][0] = b0; c[mt][nt][1] = b1;
            c[mt][nt][2] = b0; c[mt][nt][3] = b1;
        }
    }
    for (int kb = 0; kb < 16; kb++){
        unsigned ah[2][4], al[2][4];
        #pragma unroll
        for (int mt = 0; mt < 2; mt++){
            int r0 = wm*32 + mt*16 + gid;
            int c0 = kb*16 + 2*tig;
            #pragma unroll
            for (int p = 0; p < 4; p++){
                float2 x2 = *(const float2*)(smx + (r0 + (p & 1)*8)*PITCH + c0 + (p >> 1)*8);
                split2(x2.x, x2.y, ah[mt][p], al[mt][p]);
            }
        }
        #pragma unroll
        for (int nt = 0; nt < 8; nt++){
            float4 wv = __ldg(&g_Wm4[((kb*4 + 3)*32 + wn*8 + nt)*32 + lane]);
            unsigned bh[2] = { __float_as_uint(wv.x), __float_as_uint(wv.y) };
            unsigned bl[2] = { __float_as_uint(wv.z), __float_as_uint(wv.w) };
            mma3(c[0][nt], ah[0], al[0], bh, bl);
            mma3(c[1][nt], ah[1], al[1], bh, bl);
        }
    }
    #pragma unroll
    for (int mt = 0; mt < 2; mt++)
        #pragma unroll
        for (int nt = 0; nt < 8; nt++)
            g_base4[((tile*16 + warp*2 + mt)*8 + nt)*32 + lane] =
                make_float4(c[mt][nt][0], c[mt][nt][1], c[mt][nt][2], c[mt][nt][3]);
}

// ---------------- attention P·V GEMM (512 threads): out[64,256] = A[64,64]*B[64,256] ----
__device__ __forceinline__ void attn_pv(const float* __restrict__ attm, int transA,
                                        const float* __restrict__ Btile,
                                        const float* __restrict__ rscale,
                                        float* __restrict__ out, int t){
    const int lane = t & 31, warp = t >> 5;
    const int gid = lane >> 2, tig = lane & 3;
    const int wm = warp >> 3, wn = warp & 7;
    float c[2][4][4];
    #pragma unroll
    for (int mt = 0; mt < 2; mt++)
        #pragma unroll
        for (int nt = 0; nt < 4; nt++)
            #pragma unroll
            for (int i = 0; i < 4; i++) c[mt][nt][i] = 0.f;

    for (int kb = 0; kb < 4; kb++){
        unsigned ah[2][4], al[2][4];
        #pragma unroll
        for (int mt = 0; mt < 2; mt++){
            int r0 = wm*32 + mt*16 + gid;
            int c0 = kb*16 + 2*tig;
            #pragma unroll
            for (int p = 0; p < 4; p++){
                int rr = r0 + (p & 1)*8;
                int cc = c0 + (p >> 1)*8;
                float v0, v1;
                if (transA){ v0 = attm[cc*PA + rr]; v1 = attm[(cc+1)*PA + rr]; }
                else { float2 v = *(const float2*)(attm + rr*PA + cc); v0 = v.x; v1 = v.y; }
                split2(v0, v1, ah[mt][p], al[mt][p]);
            }
        }
        #pragma unroll
        for (int nt = 0; nt < 4; nt++){
            int d0 = wn*32 + nt*8 + gid;
            int k0 = kb*16 + 2*tig;
            unsigned bh[2], bl[2];
            split2(Btile[k0*PITCH + d0],     Btile[(k0+1)*PITCH + d0], bh[0], bl[0]);
            split2(Btile[(k0+8)*PITCH + d0], Btile[(k0+9)*PITCH + d0], bh[1], bl[1]);
            mma3(c[0][nt], ah[0], al[0], bh, bl);
            mma3(c[1][nt], ah[1], al[1], bh, bl);
        }
    }
    #pragma unroll
    for (int mt = 0; mt < 2; mt++){
        int r0 = wm*32 + mt*16 + gid;
        float s0 = rscale ? rscale[r0]   : 1.0f;
        float s1 = rscale ? rscale[r0+8] : 1.0f;
        #pragma unroll
        for (int nt = 0; nt < 4; nt++){
            int col = wn*32 + nt*8 + 2*tig;
            *(float2*)(out + r0*PITCH + col)     = make_float2(c[mt][nt][0]*s0, c[mt][nt][1]*s0);
            *(float2*)(out + (r0+8)*PITCH + col) = make_float2(c[mt][nt][2]*s1, c[mt][nt][3]*s1);
        }
    }
}

// ---------------- enhanced projection + mish + pool + LN (512 threads) ----------------
__device__ __forceinline__ void proj_phase(
    const float* __restrict__ xt, const float* __restrict__ at,
    const float4* __restrict__ basef,
    float* pmax, float* psum, float* pool_out,
    const float* __restrict__ ln2g, const float* __restrict__ ln2b,
    float* red, int t)
{
    const int lane = t & 31, warp = t >> 5;
    const int gid = lane >> 2, tig = lane & 3;
    const int wm = warp >> 3, wn = warp & 7;

    float c[2][4][4];
    #pragma unroll
    for (int mt = 0; mt < 2; mt++){
        int slot16 = (wm*4 + (wn >> 1))*2 + mt;
        #pragma unroll
        for (int nt = 0; nt < 4; nt++){
            int slotnt = (wn & 1)*4 + nt;
            float4 v = __ldg(&basef[(slot16*8 + slotnt)*32 + lane]);
            c[mt][nt][0] = v.x; c[mt][nt][1] = v.y; c[mt][nt][2] = v.z; c[mt][nt][3] = v.w;
        }
    }

    for (int kb = 0; kb < 16; kb++){
        float2 xv[2][4], av[2][4];
        #pragma unroll
        for (int mt = 0; mt < 2; mt++){
            int r0 = wm*32 + mt*16 + gid;
            int c0 = kb*16 + 2*tig;
            #pragma unroll
            for (int p = 0; p < 4; p++){
                int rr = r0 + (p & 1)*8;
                int cc = c0 + (p >> 1)*8;
                xv[mt][p] = *(const float2*)(xt + rr*PITCH + cc);
                av[mt][p] = *(const float2*)(at + rr*PITCH + cc);
            }
        }
        #pragma unroll
        for (int w = 0; w < 3; w++){
            unsigned ah[2][4], al[2][4];
            #pragma unroll
            for (int mt = 0; mt < 2; mt++)
                #pragma unroll
                for (int p = 0; p < 4; p++){
                    float f0, f1;
                    if (w == 0){ f0 = av[mt][p].x; f1 = av[mt][p].y; }
                    else if (w == 1){
                        f0 = fabsf(xv[mt][p].x - av[mt][p].x);
                        f1 = fabsf(xv[mt][p].y - av[mt][p].y);
                    } else {
                        f0 = xv[mt][p].x * av[mt][p].x;
                        f1 = xv[mt][p].y * av[mt][p].y;
                    }
                    split2(f0, f1, ah[mt][p], al[mt][p]);
                }
            #pragma unroll
            for (int nt = 0; nt < 4; nt++){
                int jt = wn*4 + nt;
                float4 wv = __ldg(&g_Wm4[((kb*4 + w)*32 + jt)*32 + lane]);
                unsigned bh[2] = { __float_as_uint(wv.x), __float_as_uint(wv.y) };
                unsigned bl[2] = { __float_as_uint(wv.z), __float_as_uint(wv.w) };
                mma3(c[0][nt], ah[0], al[0], bh, bl);
                mma3(c[1][nt], ah[1], al[1], bh, bl);
            }
        }
    }

    // mish + pooled max/sum; warp owns cols wn*32 + nt*8 + 2tig + e, rows wm*32..+31
    float mymax[4][2], mysum[4][2];
    #pragma unroll
    for (int nt = 0; nt < 4; nt++){
        #pragma unroll
        for (int e = 0; e < 2; e++){
            float v00 = mishf(c[0][nt][e]);
            float v01 = mishf(c[0][nt][2+e]);
            float v10 = mishf(c[1][nt][e]);
            float v11 = mishf(c[1][nt][2+e]);
            float mx = fmaxf(fmaxf(v00, v01), fmaxf(v10, v11));
            float sm = (v00 + v01) + (v10 + v11);
            #pragma unroll
            for (int off = 4; off < 32; off <<= 1){
                mx = fmaxf(mx, __shfl_xor_sync(0xffffffffu, mx, off));
                sm += __shfl_xor_sync(0xffffffffu, sm, off);
            }
            mymax[nt][e] = mx; mysum[nt][e] = sm;
        }
    }
    if (wm == 1 && gid == 0){
        #pragma unroll
        for (int nt = 0; nt < 4; nt++)
            #pragma unroll
            for (int e = 0; e < 2; e++){
                int j = wn*32 + nt*8 + 2*tig + e;
                pmax[j] = mymax[nt][e]; psum[j] = mysum[nt][e];
            }
    }
    __syncthreads();
    if (wm == 0 && gid == 0){
        #pragma unroll
        for (int nt = 0; nt < 4; nt++)
            #pragma unroll
            for (int e = 0; e < 2; e++){
                int j = wn*32 + nt*8 + 2*tig + e;
                pool_out[j]     = fmaxf(mymax[nt][e], pmax[j]);
                pool_out[D + j] = (mysum[nt][e] + psum[j]) * (1.0f/(float)Lh);
            }
    }
    __syncthreads();

    // LayerNorm over 512 (one element per thread)
    float v = pool_out[t];
    float S  = blockSum512(v,   red, t);
    float SS = blockSum512(v*v, red, t);
    float mean = S  * (1.0f/512.0f);
    float var  = SS * (1.0f/512.0f) - mean*mean;
    float inv  = rsqrtf(var + 1e-5f);
    pool_out[t] = (v - mean)*inv*ln2g[t] + ln2b[t];
    __syncthreads();
}

// ---------------- kernel D: one CTA per (query, support) pair (512 threads) ----------------
__global__ void __launch_bounds__(512, 1) k_pair(
    const float* __restrict__ ln2g, const float* __restrict__ ln2b,
    const float* __restrict__ W2,  const float* __restrict__ b2,
    const float* __restrict__ W3,  const float* __restrict__ b3,
    const float* __restrict__ b1v)
{
    extern __shared__ float sm[];
    float* s_t  = sm + SM_S;
    float* q_t  = sm + SM_Q;
    float* a_t  = sm + SM_A;
    float* att  = sm + SM_ATT;
    float* pmax = sm + SM_PMAX;
    float* psum = sm + SM_PSUM;
    float* pool = sm + SM_POOL;
    float* rmax = sm + SM_RMAX;
    float* rsum = sm + SM_RSUM;
    float* cmax = sm + SM_CMAX;
    float* csum = sm + SM_CSUM;
    float* red  = sm + SM_RED;

    const int m = blockIdx.x;
    const int b = m / (NQh*Nh);
    const int rem = m % (NQh*Nh);
    const int iq = rem / Nh;
    const int n  = rem % Nh;
    const int sIdx = b*Nh + n;      // K = 1
    const int qIdx = b*NQh + iq;
    const int t = threadIdx.x;
    const int lane = t & 31, warp = t >> 5;
    const int gid = lane >> 2, tig = lane & 3;

    // load tiles into pitched smem
    {
        const float* sp = g_sN + (size_t)sIdx*TILE_ELEMS;
        const float* qp = g_qN + (size_t)qIdx*TILE_ELEMS;
        for (int idx = t; idx < TILE_ELEMS; idx += 512){
            int row = idx >> 8, col = idx & 255;
            s_t[row*PITCH + col] = sp[idx];
            q_t[row*PITCH + col] = qp[idx];
        }
    }
    __syncthreads();

    // att[l][k] = s[l] . q[k]  (16 warps: 4x4 tiling of 16x16 output tiles)
    {
        const int wma = warp >> 2, wna = warp & 3;
        float ca[2][4];
        #pragma unroll
        for (int nt = 0; nt < 2; nt++)
            #pragma unroll
            for (int i = 0; i < 4; i++) ca[nt][i] = 0.f;
        for (int kb = 0; kb < 16; kb++){
            unsigned ah[4], al[4];
            int r0 = wma*16 + gid;
            int c0 = kb*16 + 2*tig;
            #pragma unroll
            for (int p = 0; p < 4; p++){
                float2 s2 = *(const float2*)(s_t + (r0 + (p & 1)*8)*PITCH + c0 + (p >> 1)*8);
                split2(s2.x, s2.y, ah[p], al[p]);
            }
            #pragma unroll
            for (int nt = 0; nt < 2; nt++){
                int n0 = wna*16 + nt*8 + gid;
                unsigned bh[2], bl[2];
                float2 q0 = *(const float2*)(q_t + n0*PITCH + c0);
                float2 q1 = *(const float2*)(q_t + n0*PITCH + c0 + 8);
                split2(q0.x, q0.y, bh[0], bl[0]);
                split2(q1.x, q1.y, bh[1], bl[1]);
                mma3(ca[nt], ah, al, bh, bl);
            }
        }
        #pragma unroll
        for (int nt = 0; nt < 2; nt++){
            int r0 = wma*16 + gid;
            int col = wna*16 + nt*8 + 2*tig;
            *(float2*)(att + r0*PA + col)     = make_float2(ca[nt][0], ca[nt][1]);
            *(float2*)(att + (r0+8)*PA + col) = make_float2(ca[nt][2], ca[nt][3]);
        }
    }
    __syncthreads();

    // row / column maxima
    if (t < 64){
        float mx = -3.4e38f;
        const float* row = att + t*PA;
        #pragma unroll 8
        for (int k2 = 0; k2 < 64; k2++) mx = fmaxf(mx, row[k2]);
        rmax[t] = mx;
    } else if (t < 128){
        int k = t - 64;
        float mx = -3.4e38f;
        for (int l = 0; l < 64; l++) mx = fmaxf(mx, att[l*PA + k]);
        cmax[k] = mx;
    }
    __syncthreads();

    // att := E = exp(att - rmax[l])
    {
        const int k = t & 63, l0 = t >> 6;   // l0 in 0..7
        #pragma unroll
        for (int i = 0; i < 8; i++){
            int l = l0 + 8*i;
            att[l*PA + k] = __expf(att[l*PA + k] - rmax[l]);
        }
    }
    __syncthreads();

    // row sums (reciprocal) and column sums (reciprocal, rebased to cmax)
    if (t < 64){
        float s = 0.f;
        const float* row = att + t*PA;
        #pragma unroll 8
        for (int k2 = 0; k2 < 64; k2++) s += row[k2];
        rsum[t] = 1.0f / s;
    } else if (t < 128){
        int k = t - 64;
        float cm = cmax[k];
        float s = 0.f;
        for (int l = 0; l < 64; l++){
            float h = __expf(0.5f*(rmax[l] - cm));   // split to avoid overflow
            s += att[l*PA + k] * h * h;
        }
        csum[k] = 1.0f / s;
    }
    __syncthreads();

    // s_att = (E @ Q) / rowsum  -> a_t
    attn_pv(att, 0, q_t, rsum, a_t, t);
    __syncthreads();

    // phase S -> pool[512..1023]
    proj_phase(s_t, a_t, g_base4 + (size_t)sIdx*4096,
               pmax, psum, pool + 512, ln2g, ln2b, red, t);

    // att := P_col = exp(att_raw - cmax[k]) / colsum
    {
        const int k = t & 63, l0 = t >> 6;
        float ci = csum[k], cm = cmax[k];
        #pragma unroll
        for (int i = 0; i < 8; i++){
            int l = l0 + 8*i;
            float h = __expf(0.5f*(rmax[l] - cm));
            att[l*PA + k] = att[l*PA + k] * h * h * ci;
        }
    }
    __syncthreads();

    // q_att = P_col^T @ S -> a_t
    attn_pv(att, 1, s_t, (const float*)0, a_t, t);
    __syncthreads();

    // phase Q -> pool[0..511]
    proj_phase(q_t, a_t, g_base4 + (size_t)(NSUP + qIdx)*4096,
               pmax, psum, pool, ln2g, ln2b, red, t);

    // MLP head: cat = [q_pool | s_pool] (1024); K-split over 2 thread halves
    {
        int j = t & 255, half = t >> 8;
        float acc = 0.f;
        const float* W1col = g_W1T + j;
        int c0 = half*512;
        #pragma unroll 4
        for (int c = 0; c < 512; c++)
            acc += pool[c0 + c] * W1col[(c0 + c)*D];
        if (half == 0) pmax[j] = acc; else psum[j] = acc;
        __syncthreads();
        float part = 0.f;
        if (t < 256){
            float accm = pmax[t] + psum[t] + b1v[t];
            float hv = mishf(accm);
            part = hv * W2[t];
        }
        #pragma unroll
        for (int o = 16; o > 0; o >>= 1) part += __shfl_xor_sync(0xffffffffu, part, o);
        if (lane == 0) red[warp] = part;
        __syncthreads();
        if (t == 0){
            float tot = 0.f;
            #pragma unroll
            for (int w = 0; w < 16; w++) tot += red[w];
            float h = tot + b2[0];
            g_logits[m] = mishf(h)*W3[0] + b3[0];
        }
    }
}

// ---------------- kernel E: min-append, logits layout, argmax ----------------
__global__ void k_final(float* __restrict__ out, int out_size){
    int u = threadIdx.x;
    if (u >= Bh*NQh) return;
    float v[Nh];
    float mn = 3.4e38f;
    #pragma unroll
    for (int n2 = 0; n2 < Nh; n2++){
        v[n2] = g_logits[u*Nh + n2];
        mn = fminf(mn, v[n2]);
    }
    if (out_size >= 1100){
        float best = -3.4e38f; int bi = 0;
        #pragma unroll
        for (int n2 = 0; n2 < Nh; n2++){
            out[u*(Nh+1) + n2] = v[n2];
            if (v[n2] > best){ best = v[n2]; bi = n2; }
        }
        out[u*(Nh+1) + Nh] = mn - 1.0f;
        if (out_size >= 1200) out[Bh*NQh*(Nh+1) + u] = (float)bi;
    } else if (out_size == Bh*NQh){
        float best = -3.4e38f; int bi = 0;
        #pragma unroll
        for (int n2 = 0; n2 < Nh; n2++)
            if (v[n2] > best){ best = v[n2]; bi = n2; }
        ((int*)out)[u] = bi;
    }
}

// ---------------- launch ----------------
extern "C" void kernel_launch(void* const* d_in, const int* in_sizes, int n_in,
                              void* d_out, int out_size)
{
    const float* support = (const float*)d_in[0];
    const float* query   = (const float*)d_in[1];
    const float* ln_g    = (const float*)d_in[2];
    const float* ln_b    = (const float*)d_in[3];
    const float* ln2_g   = (const float*)d_in[4];
    const float* ln2_b   = (const float*)d_in[5];
    const float* proj_W  = (const float*)d_in[6];
    const float* proj_b  = (const float*)d_in[7];
    const float* W1      = (const float*)d_in[8];
    const float* b1      = (const float*)d_in[9];
    const float* W2      = (const float*)d_in[10];
    const float* b2      = (const float*)d_in[11];
    const float* W3      = (const float*)d_in[12];
    const float* b3      = (const float*)d_in[13];

    cudaFuncSetAttribute(k_pair, cudaFuncAttributeMaxDynamicSharedMemorySize, SMEM_PAIR_BYTES);
    cudaFuncSetAttribute(k_base, cudaFuncAttributeMaxDynamicSharedMemorySize, SMEM_BASE_BYTES);

    k_ln<<<(NSUP + NQRY)*Lh, 256>>>(support, query, ln_g, ln_b);
    k_transposeW1<<<1024, 256>>>(W1);
    k_prepw<<<256, 256>>>(proj_W);
    k_base<<<NTILE, 256, SMEM_BASE_BYTES>>>(proj_b);
    k_pair<<<Mh, 512, SMEM_PAIR_BYTES>>>(ln2_g, ln2_b, W2, b2, W3, b3, b1);
    k_final<<<1, 128>>>((float*)d_out, out_size);
}

// round 5
// speedup vs baseline: 3.4791x; 1.0002x over previous
#include <cuda_runtime.h>
#include <cstdint>

#define D 256
#define Lh 64
#define Bh 2
#define Nh 10
#define NQh 50
#define Mh 1000
#define NSUP 20
#define NQRY 100
#define NTILE 120
#define PITCH 260
#define PA 68
#define TILE_ELEMS (Lh*D)

// ---------------- scratch (device globals; no allocations allowed) ----------------
__device__ float g_sN[NSUP*TILE_ELEMS];
__device__ float g_qN[NQRY*TILE_ELEMS];
__device__ float g_W1T[4*D*D];                    // W1 transposed (for MLP head)
__device__ float4 g_Wm4[16*4*32*32];              // proj_W bf16 hi/lo b-fragments (1MB)
__device__ float4 g_base4[NTILE*16*8*32];         // base = x@W0^T + b, fragment-native
__device__ float g_logits[Mh];

// Shared-memory layout (floats) for the pair kernel
#define SM_S    0
#define SM_Q    (SM_S + Lh*PITCH)
#define SM_A    (SM_Q + Lh*PITCH)
#define SM_ATT  (SM_A + Lh*PITCH)
#define SM_PMAX (SM_ATT + Lh*PA)
#define SM_PSUM (SM_PMAX + D)
#define SM_POOL (SM_PSUM + D)       // 1024: [0..511]=q_pool, [512..1023]=s_pool
#define SM_RMAX (SM_POOL + 1024)
#define SM_RSUM (SM_RMAX + 64)
#define SM_CMAX (SM_RSUM + 64)
#define SM_CSUM (SM_CMAX + 64)
#define SM_RED  (SM_CSUM + 64)
#define SM_TOTAL (SM_RED + 32)
#define SMEM_PAIR_BYTES (SM_TOTAL*4)
#define SMEM_BASE_BYTES (Lh*PITCH*4)

// ---------------- bf16 split helpers ----------------
__device__ __forceinline__ unsigned pack2(float x0, float x1){
    unsigned r; asm("cvt.rn.bf16x2.f32 %0, %1, %2;" : "=r"(r) : "f"(x1), "f"(x0)); return r;
}
__device__ __forceinline__ void split2(float x0, float x1, unsigned &h, unsigned &l){
    h = pack2(x0, x1);
    float h0 = __uint_as_float(h << 16);
    float h1 = __uint_as_float(h & 0xffff0000u);
    l = pack2(x0 - h0, x1 - h1);
}
__device__ __forceinline__ void mmab(float* c, const unsigned* a, const unsigned* b){
    asm volatile("mma.sync.aligned.m16n8k16.row.col.f32.bf16.bf16.f32 "
        "{%0,%1,%2,%3}, {%4,%5,%6,%7}, {%8,%9}, {%0,%1,%2,%3};\n"
        : "+f"(c[0]), "+f"(c[1]), "+f"(c[2]), "+f"(c[3])
        : "r"(a[0]), "r"(a[1]), "r"(a[2]), "r"(a[3]), "r"(b[0]), "r"(b[1]));
}
__device__ __forceinline__ void mma3(float* c, const unsigned* ah, const unsigned* al,
                                     const unsigned* bh, const unsigned* bl){
    mmab(c, ah, bh); mmab(c, ah, bl); mmab(c, al, bh);
}

// mish(x) = x * tanh(softplus(x)) = x * (u^2+2u)/(u^2+2u+2), u = e^x
__device__ __forceinline__ float mishf(float x){
    if (x > 20.0f) return x;
    float u = __expf(x);
    float v = u*u + 2.0f*u;
    return x * v / (v + 2.0f);
}

// block-wide sum over 512 threads (16 warps)
__device__ __forceinline__ float blockSum512(float v, float* red, int t){
    #pragma unroll
    for (int o = 16; o > 0; o >>= 1) v += __shfl_xor_sync(0xffffffffu, v, o);
    if ((t & 31) == 0) red[t >> 5] = v;
    __syncthreads();
    float s = 0.f;
    #pragma unroll
    for (int w = 0; w < 16; w++) s += red[w];
    __syncthreads();
    return s;
}

// ---------------- kernel A: row LayerNorm of support & query ----------------
__global__ void k_ln(const float* __restrict__ sup, const float* __restrict__ qry,
                     const float* __restrict__ gg, const float* __restrict__ bb){
    __shared__ float rs[8], rq[8];
    int r = blockIdx.x, t = threadIdx.x;
    const float* src; float* dst;
    const int nsr = NSUP*Lh;
    if (r < nsr){ src = sup + (size_t)r*D; dst = g_sN + (size_t)r*D; }
    else        { src = qry + (size_t)(r-nsr)*D; dst = g_qN + (size_t)(r-nsr)*D; }
    float x = src[t];
    float s = x, q = x*x;
    #pragma unroll
    for (int o = 16; o > 0; o >>= 1){
        s += __shfl_xor_sync(0xffffffffu, s, o);
        q += __shfl_xor_sync(0xffffffffu, q, o);
    }
    if ((t & 31) == 0){ rs[t>>5] = s; rq[t>>5] = q; }
    __syncthreads();
    float S = 0.f, Q2 = 0.f;
    #pragma unroll
    for (int w = 0; w < 8; w++){ S += rs[w]; Q2 += rq[w]; }
    float mu  = S  * (1.0f/D);
    float var = Q2 * (1.0f/D) - mu*mu;
    float inv = rsqrtf(var + 1e-5f);
    dst[t] = (x - mu)*inv*gg[t] + bb[t];
}

// ---------------- kernel B: transpose W1 [256][1024] -> [1024][256] ----------------
__global__ void k_transposeW1(const float* __restrict__ W){
    int c = blockIdx.x, j = threadIdx.x;
    g_W1T[c*D + j] = W[(size_t)j*1024 + c];
}

// ---------------- kernel B2: proj_W -> bf16 hi/lo b-fragments ----------------
__global__ void k_prepw(const float* __restrict__ pw){
    int idx = blockIdx.x*256 + threadIdx.x;     // 65536 total
    int lane = idx & 31;
    int jt   = (idx >> 5) & 31;
    int w    = (idx >> 10) & 3;
    int kb   = idx >> 12;
    int tig = lane & 3, gid = lane >> 2;
    int j = jt*8 + gid;
    int cblk = (w == 3) ? 0 : (w + 1);
    size_t base = (size_t)j*1024 + cblk*256 + kb*16 + 2*tig;
    unsigned bh0, bl0, bh1, bl1;
    split2(pw[base],     pw[base + 1], bh0, bl0);
    split2(pw[base + 8], pw[base + 9], bh1, bl1);
    g_Wm4[idx] = make_float4(__uint_as_float(bh0), __uint_as_float(bh1),
                             __uint_as_float(bl0), __uint_as_float(bl1));
}

// ---------------- kernel C: per-tile base = x @ W0^T + proj_b ----------------
__global__ void __launch_bounds__(256,1) k_base(const float* __restrict__ pb){
    extern __shared__ float smx[];
    int tile = blockIdx.x, t = threadIdx.x;
    const float* src = (tile < NSUP) ? (g_sN + (size_t)tile*TILE_ELEMS)
                                     : (g_qN + (size_t)(tile-NSUP)*TILE_ELEMS);
    for (int idx = t; idx < TILE_ELEMS; idx += 256){
        int row = idx >> 8, col = idx & 255;
        smx[row*PITCH + col] = src[idx];
    }
    __syncthreads();

    const int lane = t & 31, warp = t >> 5;
    const int gid = lane >> 2, tig = lane & 3;
    const int wm = warp >> 2, wn = warp & 3;

    float c[2][8][4];
    #pragma unroll
    for (int nt = 0; nt < 8; nt++){
        int col = wn*64 + nt*8 + 2*tig;
        float b0 = pb[col], b1 = pb[col+1];
        #pragma unroll
        for (int mt = 0; mt < 2; mt++){
            c[mt][nt][0] = b0; c[mt][nt][1] = b1;
            c[mt][nt][2] = b0; c[mt][nt][3] = b1;
        }
    }
    for (int kb = 0; kb < 16; kb++){
        unsigned ah[2][4], al[2][4];
        #pragma unroll
        for (int mt = 0; mt < 2; mt++){
            int r0 = wm*32 + mt*16 + gid;
            int c0 = kb*16 + 2*tig;
            #pragma unroll
            for (int p = 0; p < 4; p++){
                float2 x2 = *(const float2*)(smx + (r0 + (p & 1)*8)*PITCH + c0 + (p >> 1)*8);
                split2(x2.x, x2.y, ah[mt][p], al[mt][p]);
            }
        }
        #pragma unroll
        for (int nt = 0; nt < 8; nt++){
            float4 wv = __ldg(&g_Wm4[((kb*4 + 3)*32 + wn*8 + nt)*32 + lane]);
            unsigned bh[2] = { __float_as_uint(wv.x), __float_as_uint(wv.y) };
            unsigned bl[2] = { __float_as_uint(wv.z), __float_as_uint(wv.w) };
            mma3(c[0][nt], ah[0], al[0], bh, bl);
            mma3(c[1][nt], ah[1], al[1], bh, bl);
        }
    }
    #pragma unroll
    for (int mt = 0; mt < 2; mt++)
        #pragma unroll
        for (int nt = 0; nt < 8; nt++)
            g_base4[((tile*16 + warp*2 + mt)*8 + nt)*32 + lane] =
                make_float4(c[mt][nt][0], c[mt][nt][1], c[mt][nt][2], c[mt][nt][3]);
}

// ---------------- attention P·V GEMM (512 threads): out[64,256] = A[64,64]*B[64,256] ----
__device__ __forceinline__ void attn_pv(const float* __restrict__ attm, int transA,
                                        const float* __restrict__ Btile,
                                        const float* __restrict__ rscale,
                                        float* __restrict__ out, int t){
    const int lane = t & 31, warp = t >> 5;
    const int gid = lane >> 2, tig = lane & 3;
    const int wm = warp >> 3, wn = warp & 7;
    float c[2][4][4];
    #pragma unroll
    for (int mt = 0; mt < 2; mt++)
        #pragma unroll
        for (int nt = 0; nt < 4; nt++)
            #pragma unroll
            for (int i = 0; i < 4; i++) c[mt][nt][i] = 0.f;

    for (int kb = 0; kb < 4; kb++){
        unsigned ah[2][4], al[2][4];
        #pragma unroll
        for (int mt = 0; mt < 2; mt++){
            int r0 = wm*32 + mt*16 + gid;
            int c0 = kb*16 + 2*tig;
            #pragma unroll
            for (int p = 0; p < 4; p++){
                int rr = r0 + (p & 1)*8;
                int cc = c0 + (p >> 1)*8;
                float v0, v1;
                if (transA){ v0 = attm[cc*PA + rr]; v1 = attm[(cc+1)*PA + rr]; }
                else { float2 v = *(const float2*)(attm + rr*PA + cc); v0 = v.x; v1 = v.y; }
                split2(v0, v1, ah[mt][p], al[mt][p]);
            }
        }
        #pragma unroll
        for (int nt = 0; nt < 4; nt++){
            int d0 = wn*32 + nt*8 + gid;
            int k0 = kb*16 + 2*tig;
            unsigned bh[2], bl[2];
            split2(Btile[k0*PITCH + d0],     Btile[(k0+1)*PITCH + d0], bh[0], bl[0]);
            split2(Btile[(k0+8)*PITCH + d0], Btile[(k0+9)*PITCH + d0], bh[1], bl[1]);
            mma3(c[0][nt], ah[0], al[0], bh, bl);
            mma3(c[1][nt], ah[1], al[1], bh, bl);
        }
    }
    #pragma unroll
    for (int mt = 0; mt < 2; mt++){
        int r0 = wm*32 + mt*16 + gid;
        float s0 = rscale ? rscale[r0]   : 1.0f;
        float s1 = rscale ? rscale[r0+8] : 1.0f;
        #pragma unroll
        for (int nt = 0; nt < 4; nt++){
            int col = wn*32 + nt*8 + 2*tig;
            *(float2*)(out + r0*PITCH + col)     = make_float2(c[mt][nt][0]*s0, c[mt][nt][1]*s0);
            *(float2*)(out + (r0+8)*PITCH + col) = make_float2(c[mt][nt][2]*s1, c[mt][nt][3]*s1);
        }
    }
}

// ---------------- enhanced projection + mish + pool + LN (512 threads) ----------------
__device__ __forceinline__ void proj_phase(
    const float* __restrict__ xt, const float* __restrict__ at,
    const float4* __restrict__ basef,
    float* pmax, float* psum, float* pool_out,
    const float* __restrict__ ln2g, const float* __restrict__ ln2b,
    float* red, int t)
{
    const int lane = t & 31, warp = t >> 5;
    const int gid = lane >> 2, tig = lane & 3;
    const int wm = warp >> 3, wn = warp & 7;

    float c[2][4][4];
    #pragma unroll
    for (int mt = 0; mt < 2; mt++){
        int slot16 = (wm*4 + (wn >> 1))*2 + mt;
        #pragma unroll
        for (int nt = 0; nt < 4; nt++){
            int slotnt = (wn & 1)*4 + nt;
            float4 v = __ldg(&basef[(slot16*8 + slotnt)*32 + lane]);
            c[mt][nt][0] = v.x; c[mt][nt][1] = v.y; c[mt][nt][2] = v.z; c[mt][nt][3] = v.w;
        }
    }

    for (int kb = 0; kb < 16; kb++){
        float2 xv[2][4], av[2][4];
        #pragma unroll
        for (int mt = 0; mt < 2; mt++){
            int r0 = wm*32 + mt*16 + gid;
            int c0 = kb*16 + 2*tig;
            #pragma unroll
            for (int p = 0; p < 4; p++){
                int rr = r0 + (p & 1)*8;
                int cc = c0 + (p >> 1)*8;
                xv[mt][p] = *(const float2*)(xt + rr*PITCH + cc);
                av[mt][p] = *(const float2*)(at + rr*PITCH + cc);
            }
        }
        #pragma unroll
        for (int w = 0; w < 3; w++){
            unsigned ah[2][4], al[2][4];
            #pragma unroll
            for (int mt = 0; mt < 2; mt++)
                #pragma unroll
                for (int p = 0; p < 4; p++){
                    float f0, f1;
                    if (w == 0){ f0 = av[mt][p].x; f1 = av[mt][p].y; }
                    else if (w == 1){
                        f0 = fabsf(xv[mt][p].x - av[mt][p].x);
                        f1 = fabsf(xv[mt][p].y - av[mt][p].y);
                    } else {
                        f0 = xv[mt][p].x * av[mt][p].x;
                        f1 = xv[mt][p].y * av[mt][p].y;
                    }
                    split2(f0, f1, ah[mt][p], al[mt][p]);
                }
            #pragma unroll
            for (int nt = 0; nt < 4; nt++){
                int jt = wn*4 + nt;
                float4 wv = __ldg(&g_Wm4[((kb*4 + w)*32 + jt)*32 + lane]);
                unsigned bh[2] = { __float_as_uint(wv.x), __float_as_uint(wv.y) };
                unsigned bl[2] = { __float_as_uint(wv.z), __float_as_uint(wv.w) };
                mma3(c[0][nt], ah[0], al[0], bh, bl);
                mma3(c[1][nt], ah[1], al[1], bh, bl);
            }
        }
    }

    // mish + pooled max/sum; warp owns cols wn*32 + nt*8 + 2tig + e, rows wm*32..+31
    float mymax[4][2], mysum[4][2];
    #pragma unroll
    for (int nt = 0; nt < 4; nt++){
        #pragma unroll
        for (int e = 0; e < 2; e++){
            float v00 = mishf(c[0][nt][e]);
            float v01 = mishf(c[0][nt][2+e]);
            float v10 = mishf(c[1][nt][e]);
            float v11 = mishf(c[1][nt][2+e]);
            float mx = fmaxf(fmaxf(v00, v01), fmaxf(v10, v11));
            float sm = (v00 + v01) + (v10 + v11);
            #pragma unroll
            for (int off = 4; off < 32; off <<= 1){
                mx = fmaxf(mx, __shfl_xor_sync(0xffffffffu, mx, off));
                sm += __shfl_xor_sync(0xffffffffu, sm, off);
            }
            mymax[nt][e] = mx; mysum[nt][e] = sm;
        }
    }
    if (wm == 1 && gid == 0){
        #pragma unroll
        for (int nt = 0; nt < 4; nt++)
            #pragma unroll
            for (int e = 0; e < 2; e++){
                int j = wn*32 + nt*8 + 2*tig + e;
                pmax[j] = mymax[nt][e]; psum[j] = mysum[nt][e];
            }
    }
    __syncthreads();
    if (wm == 0 && gid == 0){
        #pragma unroll
        for (int nt = 0; nt < 4; nt++)
            #pragma unroll
            for (int e = 0; e < 2; e++){
                int j = wn*32 + nt*8 + 2*tig + e;
                pool_out[j]     = fmaxf(mymax[nt][e], pmax[j]);
                pool_out[D + j] = (mysum[nt][e] + psum[j]) * (1.0f/(float)Lh);
            }
    }
    __syncthreads();

    // LayerNorm over 512 (one element per thread)
    float v = pool_out[t];
    float S  = blockSum512(v,   red, t);
    float SS = blockSum512(v*v, red, t);
    float mean = S  * (1.0f/512.0f);
    float var  = SS * (1.0f/512.0f) - mean*mean;
    float inv  = rsqrtf(var + 1e-5f);
    pool_out[t] = (v - mean)*inv*ln2g[t] + ln2b[t];
    __syncthreads();
}

// ---------------- kernel D: one CTA per (query, support) pair (512 threads) ----------------
__global__ void __launch_bounds__(512, 1) k_pair(
    const float* __restrict__ ln2g, const float* __restrict__ ln2b,
    const float* __restrict__ W2,  const float* __restrict__ b2,
    const float* __restrict__ W3,  const float* __restrict__ b3,
    const float* __restrict__ b1v)
{
    extern __shared__ float sm[];
    float* s_t  = sm + SM_S;
    float* q_t  = sm + SM_Q;
    float* a_t  = sm + SM_A;
    float* att  = sm + SM_ATT;
    float* pmax = sm + SM_PMAX;
    float* psum = sm + SM_PSUM;
    float* pool = sm + SM_POOL;
    float* rmax = sm + SM_RMAX;
    float* rsum = sm + SM_RSUM;
    float* cmax = sm + SM_CMAX;
    float* csum = sm + SM_CSUM;
    float* red  = sm + SM_RED;

    const int m = blockIdx.x;
    const int b = m / (NQh*Nh);
    const int rem = m % (NQh*Nh);
    const int iq = rem / Nh;
    const int n  = rem % Nh;
    const int sIdx = b*Nh + n;      // K = 1
    const int qIdx = b*NQh + iq;
    const int t = threadIdx.x;
    const int lane = t & 31, warp = t >> 5;
    const int gid = lane >> 2, tig = lane & 3;

    // load tiles into pitched smem
    {
        const float* sp = g_sN + (size_t)sIdx*TILE_ELEMS;
        const float* qp = g_qN + (size_t)qIdx*TILE_ELEMS;
        for (int idx = t; idx < TILE_ELEMS; idx += 512){
            int row = idx >> 8, col = idx & 255;
            s_t[row*PITCH + col] = sp[idx];
            q_t[row*PITCH + col] = qp[idx];
        }
    }
    __syncthreads();

    // att[l][k] = s[l] . q[k]  (16 warps: 4x4 tiling of 16x16 output tiles)
    {
        const int wma = warp >> 2, wna = warp & 3;
        float ca[2][4];
        #pragma unroll
        for (int nt = 0; nt < 2; nt++)
            #pragma unroll
            for (int i = 0; i < 4; i++) ca[nt][i] = 0.f;
        for (int kb = 0; kb < 16; kb++){
            unsigned ah[4], al[4];
            int r0 = wma*16 + gid;
            int c0 = kb*16 + 2*tig;
            #pragma unroll
            for (int p = 0; p < 4; p++){
                float2 s2 = *(const float2*)(s_t + (r0 + (p & 1)*8)*PITCH + c0 + (p >> 1)*8);
                split2(s2.x, s2.y, ah[p], al[p]);
            }
            #pragma unroll
            for (int nt = 0; nt < 2; nt++){
                int n0 = wna*16 + nt*8 + gid;
                unsigned bh[2], bl[2];
                float2 q0 = *(const float2*)(q_t + n0*PITCH + c0);
                float2 q1 = *(const float2*)(q_t + n0*PITCH + c0 + 8);
                split2(q0.x, q0.y, bh[0], bl[0]);
                split2(q1.x, q1.y, bh[1], bl[1]);
                mma3(ca[nt], ah, al, bh, bl);
            }
        }
        #pragma unroll
        for (int nt = 0; nt < 2; nt++){
            int r0 = wma*16 + gid;
            int col = wna*16 + nt*8 + 2*tig;
            *(float2*)(att + r0*PA + col)     = make_float2(ca[nt][0], ca[nt][1]);
            *(float2*)(att + (r0+8)*PA + col) = make_float2(ca[nt][2], ca[nt][3]);
        }
    }
    __syncthreads();

    // row / column maxima
    if (t < 64){
        float mx = -3.4e38f;
        const float* row = att + t*PA;
        #pragma unroll 8
        for (int k2 = 0; k2 < 64; k2++) mx = fmaxf(mx, row[k2]);
        rmax[t] = mx;
    } else if (t < 128){
        int k = t - 64;
        float mx = -3.4e38f;
        for (int l = 0; l < 64; l++) mx = fmaxf(mx, att[l*PA + k]);
        cmax[k] = mx;
    }
    __syncthreads();

    // att := E = exp(att - rmax[l])
    {
        const int k = t & 63, l0 = t >> 6;   // l0 in 0..7
        #pragma unroll
        for (int i = 0; i < 8; i++){
            int l = l0 + 8*i;
            att[l*PA + k] = __expf(att[l*PA + k] - rmax[l]);
        }
    }
    __syncthreads();

    // row sums (reciprocal) and column sums (reciprocal, rebased to cmax)
    if (t < 64){
        float s = 0.f;
        const float* row = att + t*PA;
        #pragma unroll 8
        for (int k2 = 0; k2 < 64; k2++) s += row[k2];
        rsum[t] = 1.0f / s;
    } else if (t < 128){
        int k = t - 64;
        float cm = cmax[k];
        float s = 0.f;
        for (int l = 0; l < 64; l++){
            float h = __expf(0.5f*(rmax[l] - cm));   // split to avoid overflow
            s += att[l*PA + k] * h * h;
        }
        csum[k] = 1.0f / s;
    }
    __syncthreads();

    // s_att = (E @ Q) / rowsum  -> a_t
    attn_pv(att, 0, q_t, rsum, a_t, t);
    __syncthreads();

    // phase S -> pool[512..1023]
    proj_phase(s_t, a_t, g_base4 + (size_t)sIdx*4096,
               pmax, psum, pool + 512, ln2g, ln2b, red, t);

    // att := P_col = exp(att_raw - cmax[k]) / colsum
    {
        const int k = t & 63, l0 = t >> 6;
        float ci = csum[k], cm = cmax[k];
        #pragma unroll
        for (int i = 0; i < 8; i++){
            int l = l0 + 8*i;
            float h = __expf(0.5f*(rmax[l] - cm));
            att[l*PA + k] = att[l*PA + k] * h * h * ci;
        }
    }
    __syncthreads();

    // q_att = P_col^T @ S -> a_t
    attn_pv(att, 1, s_t, (const float*)0, a_t, t);
    __syncthreads();

    // phase Q -> pool[0..511]
    proj_phase(q_t, a_t, g_base4 + (size_t)(NSUP + qIdx)*4096,
               pmax, psum, pool, ln2g, ln2b, red, t);

    // MLP head: cat = [q_pool | s_pool] (1024); K-split over 2 thread halves
    {
        int j = t & 255, half = t >> 8;
        float acc = 0.f;
        const float* W1col = g_W1T + j;
        int c0 = half*512;
        #pragma unroll 4
        for (int c = 0; c < 512; c++)
            acc += pool[c0 + c] * W1col[(c0 + c)*D];
        if (half == 0) pmax[j] = acc; else psum[j] = acc;
        __syncthreads();
        float part = 0.f;
        if (t < 256){
            float accm = pmax[t] + psum[t] + b1v[t];
            float hv = mishf(accm);
            part = hv * W2[t];
        }
        #pragma unroll
        for (int o = 16; o > 0; o >>= 1) part += __shfl_xor_sync(0xffffffffu, part, o);
        if (lane == 0) red[warp] = part;
        __syncthreads();
        if (t == 0){
            float tot = 0.f;
            #pragma unroll
            for (int w = 0; w < 16; w++) tot += red[w];
            float h = tot + b2[0];
            g_logits[m] = mishf(h)*W3[0] + b3[0];
        }
    }
}

// ---------------- kernel E: min-append, logits layout, argmax ----------------
__global__ void k_final(float* __restrict__ out, int out_size){
    int u = threadIdx.x;
    if (u >= Bh*NQh) return;
    float v[Nh];
    float mn = 3.4e38f;
    #pragma unroll
    for (int n2 = 0; n2 < Nh; n2++){
        v[n2] = g_logits[u*Nh + n2];
        mn = fminf(mn, v[n2]);
    }
    if (out_size >= 1100){
        float best = -3.4e38f; int bi = 0;
        #pragma unroll
        for (int n2 = 0; n2 < Nh; n2++){
            out[u*(Nh+1) + n2] = v[n2];
            if (v[n2] > best){ best = v[n2]; bi = n2; }
        }
        out[u*(Nh+1) + Nh] = mn - 1.0f;
        if (out_size >= 1200) out[Bh*NQh*(Nh+1) + u] = (float)bi;
    } else if (out_size == Bh*NQh){
        float best = -3.4e38f; int bi = 0;
        #pragma unroll
        for (int n2 = 0; n2 < Nh; n2++)
            if (v[n2] > best){ best = v[n2]; bi = n2; }
        ((int*)out)[u] = bi;
    }
}

// ---------------- launch ----------------
extern "C" void kernel_launch(void* const* d_in, const int* in_sizes, int n_in,
                              void* d_out, int out_size)
{
    const float* support = (const float*)d_in[0];
    const float* query   = (const float*)d_in[1];
    const float* ln_g    = (const float*)d_in[2];
    const float* ln_b    = (const float*)d_in[3];
    const float* ln2_g   = (const float*)d_in[4];
    const float* ln2_b   = (const float*)d_in[5];
    const float* proj_W  = (const float*)d_in[6];
    const float* proj_b  = (const float*)d_in[7];
    const float* W1      = (const float*)d_in[8];
    const float* b1      = (const float*)d_in[9];
    const float* W2      = (const float*)d_in[10];
    const float* b2      = (const float*)d_in[11];
    const float* W3      = (const float*)d_in[12];
    const float* b3      = (const float*)d_in[13];

    cudaFuncSetAttribute(k_pair, cudaFuncAttributeMaxDynamicSharedMemorySize, SMEM_PAIR_BYTES);
    cudaFuncSetAttribute(k_base, cudaFuncAttributeMaxDynamicSharedMemorySize, SMEM_BASE_BYTES);

    k_ln<<<(NSUP + NQRY)*Lh, 256>>>(support, query, ln_g, ln_b);
    k_transposeW1<<<1024, 256>>>(W1);
    k_prepw<<<256, 256>>>(proj_W);
    k_base<<<NTILE, 256, SMEM_BASE_BYTES>>>(proj_b);
    k_pair<<<Mh, 512, SMEM_PAIR_BYTES>>>(ln2_g, ln2_b, W2, b2, W3, b3, b1);
    k_final<<<1, 128>>>((float*)d_out, out_size);
}

// round 6
// speedup vs baseline: 4.4348x; 1.2747x over previous
#include <cuda_runtime.h>
#include <cstdint>

#define D 256
#define Lh 64
#define Bh 2
#define Nh 10
#define NQh 50
#define Mh 1000
#define NSUP 20
#define NQRY 100
#define NTILE 120
#define PITCH 260
#define PA 68
#define TILE_ELEMS (Lh*D)

// ---------------- scratch (device globals; no allocations allowed) ----------------
__device__ float g_sN[NSUP*TILE_ELEMS];
__device__ float g_qN[NQRY*TILE_ELEMS];
__device__ float g_W1T[4*D*D];                    // W1 transposed (for MLP head)
__device__ float4 g_Wm4[16*4*32*32];              // proj_W bf16 hi/lo b-fragments (1MB)
__device__ float4 g_baseF[NTILE*4*32*32];         // base = x@W0^T + b, fragment-native fp32
__device__ float g_Y1f[NTILE*TILE_ELEMS];         // scratch: Y1 = x@W1blk fp32
__device__ uint2 g_Y1sp[NTILE*256*32];            // Y1 split bf16 hi/lo, [tile][d][kpair]
__device__ float g_pool[Mh*1024];                 // pooled+LN'd cat vectors
__device__ float g_logits[Mh];

// Shared-memory layout (floats) for the pair kernel
#define SM_S    0
#define SM_Q    (SM_S + Lh*PITCH)
#define SM_A    (SM_Q + Lh*PITCH)
#define SM_ATT  (SM_A + Lh*PITCH)
#define SM_PMAX (SM_ATT + Lh*PA)
#define SM_PSUM (SM_PMAX + D)
#define SM_POOL (SM_PSUM + D)       // 1024: [0..511]=q_pool, [512..1023]=s_pool
#define SM_RMAX (SM_POOL + 1024)
#define SM_RSUM (SM_RMAX + 64)
#define SM_CMAX (SM_RSUM + 64)
#define SM_CSUM (SM_CMAX + 64)
#define SM_RED  (SM_CSUM + 64)
#define SM_TOTAL (SM_RED + 32)
#define SMEM_PAIR_BYTES (SM_TOTAL*4)
#define SMEM_BASE_BYTES (Lh*PITCH*4)

// ---------------- bf16 split helpers ----------------
__device__ __forceinline__ unsigned pack2(float x0, float x1){
    unsigned r; asm("cvt.rn.bf16x2.f32 %0, %1, %2;" : "=r"(r) : "f"(x1), "f"(x0)); return r;
}
__device__ __forceinline__ void split2(float x0, float x1, unsigned &h, unsigned &l){
    h = pack2(x0, x1);
    float h0 = __uint_as_float(h << 16);
    float h1 = __uint_as_float(h & 0xffff0000u);
    l = pack2(x0 - h0, x1 - h1);
}
__device__ __forceinline__ void mmab(float* c, const unsigned* a, const unsigned* b){
    asm volatile("mma.sync.aligned.m16n8k16.row.col.f32.bf16.bf16.f32 "
        "{%0,%1,%2,%3}, {%4,%5,%6,%7}, {%8,%9}, {%0,%1,%2,%3};\n"
        : "+f"(c[0]), "+f"(c[1]), "+f"(c[2]), "+f"(c[3])
        : "r"(a[0]), "r"(a[1]), "r"(a[2]), "r"(a[3]), "r"(b[0]), "r"(b[1]));
}
__device__ __forceinline__ void mma3(float* c, const unsigned* ah, const unsigned* al,
                                     const unsigned* bh, const unsigned* bl){
    mmab(c, ah, bh); mmab(c, ah, bl); mmab(c, al, bh);
}

// mish(x) = x * tanh(softplus(x)) = x * (u^2+2u)/(u^2+2u+2), u = e^x
__device__ __forceinline__ float mishf(float x){
    if (x > 20.0f) return x;
    float u = __expf(x);
    float v = u*u + 2.0f*u;
    return x * v / (v + 2.0f);
}

// block-wide sum over 512 threads (16 warps)
__device__ __forceinline__ float blockSum512(float v, float* red, int t){
    #pragma unroll
    for (int o = 16; o > 0; o >>= 1) v += __shfl_xor_sync(0xffffffffu, v, o);
    if ((t & 31) == 0) red[t >> 5] = v;
    __syncthreads();
    float s = 0.f;
    #pragma unroll
    for (int w = 0; w < 16; w++) s += red[w];
    __syncthreads();
    return s;
}

// ---------------- kernel A: row LayerNorm of support & query ----------------
__global__ void k_ln(const float* __restrict__ sup, const float* __restrict__ qry,
                     const float* __restrict__ gg, const float* __restrict__ bb){
    __shared__ float rs[8], rq[8];
    int r = blockIdx.x, t = threadIdx.x;
    const float* src; float* dst;
    const int nsr = NSUP*Lh;
    if (r < nsr){ src = sup + (size_t)r*D; dst = g_sN + (size_t)r*D; }
    else        { src = qry + (size_t)(r-nsr)*D; dst = g_qN + (size_t)(r-nsr)*D; }
    float x = src[t];
    float s = x, q = x*x;
    #pragma unroll
    for (int o = 16; o > 0; o >>= 1){
        s += __shfl_xor_sync(0xffffffffu, s, o);
        q += __shfl_xor_sync(0xffffffffu, q, o);
    }
    if ((t & 31) == 0){ rs[t>>5] = s; rq[t>>5] = q; }
    __syncthreads();
    float S = 0.f, Q2 = 0.f;
    #pragma unroll
    for (int w = 0; w < 8; w++){ S += rs[w]; Q2 += rq[w]; }
    float mu  = S  * (1.0f/D);
    float var = Q2 * (1.0f/D) - mu*mu;
    float inv = rsqrtf(var + 1e-5f);
    dst[t] = (x - mu)*inv*gg[t] + bb[t];
}

// ---------------- kernel B: transpose W1 [256][1024] -> [1024][256] ----------------
__global__ void k_transposeW1(const float* __restrict__ W){
    int c = blockIdx.x, j = threadIdx.x;
    g_W1T[c*D + j] = W[(size_t)j*1024 + c];
}

// ---------------- kernel B2: proj_W -> bf16 hi/lo b-fragments ----------------
// w = 0 -> block1 (a-term, used for Y1 precompute); w = 1,2 -> blocks 2,3; w = 3 -> block 0 (base)
__global__ void k_prepw(const float* __restrict__ pw){
    int idx = blockIdx.x*256 + threadIdx.x;     // 65536 total
    int lane = idx & 31;
    int jt   = (idx >> 5) & 31;
    int w    = (idx >> 10) & 3;
    int kb   = idx >> 12;
    int tig = lane & 3, gid = lane >> 2;
    int j = jt*8 + gid;
    int cblk = (w == 3) ? 0 : (w + 1);
    size_t base = (size_t)j*1024 + cblk*256 + kb*16 + 2*tig;
    unsigned bh0, bl0, bh1, bl1;
    split2(pw[base],     pw[base + 1], bh0, bl0);
    split2(pw[base + 8], pw[base + 9], bh1, bl1);
    g_Wm4[idx] = make_float4(__uint_as_float(bh0), __uint_as_float(bh1),
                             __uint_as_float(bl0), __uint_as_float(bl1));
}

// ---------------- kernel C: per-tile base (fragment layout) + Y1 = x@W1blk (fp32 scratch) ----
__global__ void __launch_bounds__(256,1) k_base(const float* __restrict__ pb){
    extern __shared__ float smx[];
    int tile = blockIdx.x, t = threadIdx.x;
    const float* src = (tile < NSUP) ? (g_sN + (size_t)tile*TILE_ELEMS)
                                     : (g_qN + (size_t)(tile-NSUP)*TILE_ELEMS);
    for (int idx = t; idx < TILE_ELEMS; idx += 256){
        int row = idx >> 8, col = idx & 255;
        smx[row*PITCH + col] = src[idx];
    }
    __syncthreads();

    const int lane = t & 31, warp = t >> 5;
    const int gid = lane >> 2, tig = lane & 3;
    const int wm = warp >> 2, wn = warp & 3;

    // ---- pass 1: base = x @ W0^T + b ----
    {
        float c[2][8][4];
        #pragma unroll
        for (int nt = 0; nt < 8; nt++){
            int col = wn*64 + nt*8 + 2*tig;
            float b0 = pb[col], b1 = pb[col+1];
            #pragma unroll
            for (int mt = 0; mt < 2; mt++){
                c[mt][nt][0] = b0; c[mt][nt][1] = b1;
                c[mt][nt][2] = b0; c[mt][nt][3] = b1;
            }
        }
        for (int kb = 0; kb < 16; kb++){
            unsigned ah[2][4], al[2][4];
            #pragma unroll
            for (int mt = 0; mt < 2; mt++){
                int r0 = wm*32 + mt*16 + gid;
                int c0 = kb*16 + 2*tig;
                #pragma unroll
                for (int p = 0; p < 4; p++){
                    float2 x2 = *(const float2*)(smx + (r0 + (p & 1)*8)*PITCH + c0 + (p >> 1)*8);
                    split2(x2.x, x2.y, ah[mt][p], al[mt][p]);
                }
            }
            #pragma unroll
            for (int nt = 0; nt < 8; nt++){
                float4 wv = __ldg(&g_Wm4[((kb*4 + 3)*32 + wn*8 + nt)*32 + lane]);
                unsigned bh[2] = { __float_as_uint(wv.x), __float_as_uint(wv.y) };
                unsigned bl[2] = { __float_as_uint(wv.z), __float_as_uint(wv.w) };
                mma3(c[0][nt], ah[0], al[0], bh, bl);
                mma3(c[1][nt], ah[1], al[1], bh, bl);
            }
        }
        // store fragment-native: index ((tile*4 + r16)*32 + j8)*32 + lane
        #pragma unroll
        for (int mt = 0; mt < 2; mt++){
            int r16 = wm*2 + mt;
            #pragma unroll
            for (int nt = 0; nt < 8; nt++){
                int j8 = wn*8 + nt;
                g_baseF[((tile*4 + r16)*32 + j8)*32 + lane] =
                    make_float4(c[mt][nt][0], c[mt][nt][1], c[mt][nt][2], c[mt][nt][3]);
            }
        }
    }

    // ---- pass 2: Y1 = x @ W1blk^T  (proj block 1), fp32 scratch ----
    {
        float c[2][8][4];
        #pragma unroll
        for (int mt = 0; mt < 2; mt++)
            #pragma unroll
            for (int nt = 0; nt < 8; nt++)
                #pragma unroll
                for (int i = 0; i < 4; i++) c[mt][nt][i] = 0.f;
        for (int kb = 0; kb < 16; kb++){
            unsigned ah[2][4], al[2][4];
            #pragma unroll
            for (int mt = 0; mt < 2; mt++){
                int r0 = wm*32 + mt*16 + gid;
                int c0 = kb*16 + 2*tig;
                #pragma unroll
                for (int p = 0; p < 4; p++){
                    float2 x2 = *(const float2*)(smx + (r0 + (p & 1)*8)*PITCH + c0 + (p >> 1)*8);
                    split2(x2.x, x2.y, ah[mt][p], al[mt][p]);
                }
            }
            #pragma unroll
            for (int nt = 0; nt < 8; nt++){
                float4 wv = __ldg(&g_Wm4[((kb*4 + 0)*32 + wn*8 + nt)*32 + lane]);
                unsigned bh[2] = { __float_as_uint(wv.x), __float_as_uint(wv.y) };
                unsigned bl[2] = { __float_as_uint(wv.z), __float_as_uint(wv.w) };
                mma3(c[0][nt], ah[0], al[0], bh, bl);
                mma3(c[1][nt], ah[1], al[1], bh, bl);
            }
        }
        float* dst = g_Y1f + (size_t)tile*TILE_ELEMS;
        #pragma unroll
        for (int mt = 0; mt < 2; mt++){
            int r0 = wm*32 + mt*16 + gid;
            #pragma unroll
            for (int nt = 0; nt < 8; nt++){
                int col = wn*64 + nt*8 + 2*tig;
                *(float2*)(dst + r0*D + col)     = make_float2(c[mt][nt][0], c[mt][nt][1]);
                *(float2*)(dst + (r0+8)*D + col) = make_float2(c[mt][nt][2], c[mt][nt][3]);
            }
        }
    }
}

// ---------------- kernel C2: split Y1 along seq dim -> g_Y1sp[tile][d][kpair] ----------------
__global__ void k_prepY1(){
    int idx = blockIdx.x*256 + threadIdx.x;   // NTILE*8192
    int tile = idx >> 13;
    int rem  = idx & 8191;
    int d  = rem >> 5;
    int kp = rem & 31;
    const float* Y = g_Y1f + (size_t)tile*TILE_ELEMS;
    float y0 = Y[(2*kp)*D + d];
    float y1 = Y[(2*kp+1)*D + d];
    unsigned h, l; split2(y0, y1, h, l);
    g_Y1sp[idx] = make_uint2(h, l);
}

// ---------------- attention P·V GEMM (512 threads): out[64,256] = A[64,64]*B[64,256] ----
__device__ __forceinline__ void attn_pv(const float* __restrict__ attm, int transA,
                                        const float* __restrict__ Btile,
                                        const float* __restrict__ rscale,
                                        float* __restrict__ out, int t){
    const int lane = t & 31, warp = t >> 5;
    const int gid = lane >> 2, tig = lane & 3;
    const int wm = warp >> 3, wn = warp & 7;
    float c[2][4][4];
    #pragma unroll
    for (int mt = 0; mt < 2; mt++)
        #pragma unroll
        for (int nt = 0; nt < 4; nt++)
            #pragma unroll
            for (int i = 0; i < 4; i++) c[mt][nt][i] = 0.f;

    for (int kb = 0; kb < 4; kb++){
        unsigned ah[2][4], al[2][4];
        #pragma unroll
        for (int mt = 0; mt < 2; mt++){
            int r0 = wm*32 + mt*16 + gid;
            int c0 = kb*16 + 2*tig;
            #pragma unroll
            for (int p = 0; p < 4; p++){
                int rr = r0 + (p & 1)*8;
                int cc = c0 + (p >> 1)*8;
                float v0, v1;
                if (transA){ v0 = attm[cc*PA + rr]; v1 = attm[(cc+1)*PA + rr]; }
                else { float2 v = *(const float2*)(attm + rr*PA + cc); v0 = v.x; v1 = v.y; }
                split2(v0, v1, ah[mt][p], al[mt][p]);
            }
        }
        #pragma unroll
        for (int nt = 0; nt < 4; nt++){
            int d0 = wn*32 + nt*8 + gid;
            int k0 = kb*16 + 2*tig;
            unsigned bh[2], bl[2];
            split2(Btile[k0*PITCH + d0],     Btile[(k0+1)*PITCH + d0], bh[0], bl[0]);
            split2(Btile[(k0+8)*PITCH + d0], Btile[(k0+9)*PITCH + d0], bh[1], bl[1]);
            mma3(c[0][nt], ah[0], al[0], bh, bl);
            mma3(c[1][nt], ah[1], al[1], bh, bl);
        }
    }
    #pragma unroll
    for (int mt = 0; mt < 2; mt++){
        int r0 = wm*32 + mt*16 + gid;
        float s0 = rscale ? rscale[r0]   : 1.0f;
        float s1 = rscale ? rscale[r0+8] : 1.0f;
        #pragma unroll
        for (int nt = 0; nt < 4; nt++){
            int col = wn*32 + nt*8 + 2*tig;
            *(float2*)(out + r0*PITCH + col)     = make_float2(c[mt][nt][0]*s0, c[mt][nt][1]*s0);
            *(float2*)(out + (r0+8)*PITCH + col) = make_float2(c[mt][nt][2]*s1, c[mt][nt][3]*s1);
        }
    }
}

// ---------------- attn @ Y1 GEMM into registers (c2), fragment layout matches proj ----------
__device__ __forceinline__ void attn_y1(const float* __restrict__ attm, int transA,
                                        const uint2* __restrict__ y1sp,
                                        const float* __restrict__ rscale,
                                        float c2[2][4][4], int t){
    const int lane = t & 31, warp = t >> 5;
    const int gid = lane >> 2, tig = lane & 3;
    const int wm = warp >> 3, wn = warp & 7;
    #pragma unroll
    for (int mt = 0; mt < 2; mt++)
        #pragma unroll
        for (int nt = 0; nt < 4; nt++)
            #pragma unroll
            for (int i = 0; i < 4; i++) c2[mt][nt][i] = 0.f;

    for (int kb = 0; kb < 4; kb++){
        unsigned ah[2][4], al[2][4];
        #pragma unroll
        for (int mt = 0; mt < 2; mt++){
            int r0 = wm*32 + mt*16 + gid;
            int c0 = kb*16 + 2*tig;
            #pragma unroll
            for (int p = 0; p < 4; p++){
                int rr = r0 + (p & 1)*8;
                int cc = c0 + (p >> 1)*8;
                float v0, v1;
                if (transA){ v0 = attm[cc*PA + rr]; v1 = attm[(cc+1)*PA + rr]; }
                else { float2 v = *(const float2*)(attm + rr*PA + cc); v0 = v.x; v1 = v.y; }
                split2(v0, v1, ah[mt][p], al[mt][p]);
            }
        }
        #pragma unroll
        for (int nt = 0; nt < 4; nt++){
            int d0 = wn*32 + nt*8 + gid;
            int kp = kb*8 + tig;
            uint2 u0 = __ldg(&y1sp[d0*32 + kp]);
            uint2 u1 = __ldg(&y1sp[d0*32 + kp + 4]);
            unsigned bh[2] = { u0.x, u1.x };
            unsigned bl[2] = { u0.y, u1.y };
            mma3(c2[0][nt], ah[0], al[0], bh, bl);
            mma3(c2[1][nt], ah[1], al[1], bh, bl);
        }
    }
    if (rscale){
        #pragma unroll
        for (int mt = 0; mt < 2; mt++){
            int r0 = wm*32 + mt*16 + gid;
            float s0 = rscale[r0], s1 = rscale[r0+8];
            #pragma unroll
            for (int nt = 0; nt < 4; nt++){
                c2[mt][nt][0] *= s0; c2[mt][nt][1] *= s0;
                c2[mt][nt][2] *= s1; c2[mt][nt][3] *= s1;
            }
        }
    }
}

// ---------------- enhanced projection (2 features) + mish + pool + LN (512 threads) ----------
__device__ __forceinline__ void proj_phase(
    const float* __restrict__ xt, const float* __restrict__ at,
    const float4* __restrict__ basef, const float c2[2][4][4],
    float* pmax, float* psum, float* pool_out,
    const float* __restrict__ ln2g, const float* __restrict__ ln2b,
    float* red, int t)
{
    const int lane = t & 31, warp = t >> 5;
    const int gid = lane >> 2, tig = lane & 3;
    const int wm = warp >> 3, wn = warp & 7;

    float c[2][4][4];
    #pragma unroll
    for (int mt = 0; mt < 2; mt++){
        int r16 = wm*2 + mt;
        #pragma unroll
        for (int nt = 0; nt < 4; nt++){
            int j8 = wn*4 + nt;
            float4 v = __ldg(&basef[(r16*32 + j8)*32 + lane]);
            c[mt][nt][0] = v.x + c2[mt][nt][0];
            c[mt][nt][1] = v.y + c2[mt][nt][1];
            c[mt][nt][2] = v.z + c2[mt][nt][2];
            c[mt][nt][3] = v.w + c2[mt][nt][3];
        }
    }

    for (int kb = 0; kb < 16; kb++){
        float2 xv[2][4], av[2][4];
        #pragma unroll
        for (int mt = 0; mt < 2; mt++){
            int r0 = wm*32 + mt*16 + gid;
            int c0 = kb*16 + 2*tig;
            #pragma unroll
            for (int p = 0; p < 4; p++){
                int rr = r0 + (p & 1)*8;
                int cc = c0 + (p >> 1)*8;
                xv[mt][p] = *(const float2*)(xt + rr*PITCH + cc);
                av[mt][p] = *(const float2*)(at + rr*PITCH + cc);
            }
        }
        #pragma unroll
        for (int w = 1; w < 3; w++){
            unsigned ah[2][4], al[2][4];
            #pragma unroll
            for (int mt = 0; mt < 2; mt++)
                #pragma unroll
                for (int p = 0; p < 4; p++){
                    float f0, f1;
                    if (w == 1){
                        f0 = fabsf(xv[mt][p].x - av[mt][p].x);
                        f1 = fabsf(xv[mt][p].y - av[mt][p].y);
                    } else {
                        f0 = xv[mt][p].x * av[mt][p].x;
                        f1 = xv[mt][p].y * av[mt][p].y;
                    }
                    split2(f0, f1, ah[mt][p], al[mt][p]);
                }
            #pragma unroll
            for (int nt = 0; nt < 4; nt++){
                int jt = wn*4 + nt;
                float4 wv = __ldg(&g_Wm4[((kb*4 + w)*32 + jt)*32 + lane]);
                unsigned bh[2] = { __float_as_uint(wv.x), __float_as_uint(wv.y) };
                unsigned bl[2] = { __float_as_uint(wv.z), __float_as_uint(wv.w) };
                mma3(c[0][nt], ah[0], al[0], bh, bl);
                mma3(c[1][nt], ah[1], al[1], bh, bl);
            }
        }
    }

    // mish + pooled max/sum; warp owns cols wn*32 + nt*8 + 2tig + e, rows wm*32..+31
    float mymax[4][2], mysum[4][2];
    #pragma unroll
    for (int nt = 0; nt < 4; nt++){
        #pragma unroll
        for (int e = 0; e < 2; e++){
            float v00 = mishf(c[0][nt][e]);
            float v01 = mishf(c[0][nt][2+e]);
            float v10 = mishf(c[1][nt][e]);
            float v11 = mishf(c[1][nt][2+e]);
            float mx = fmaxf(fmaxf(v00, v01), fmaxf(v10, v11));
            float sm = (v00 + v01) + (v10 + v11);
            #pragma unroll
            for (int off = 4; off < 32; off <<= 1){
                mx = fmaxf(mx, __shfl_xor_sync(0xffffffffu, mx, off));
                sm += __shfl_xor_sync(0xffffffffu, sm, off);
            }
            mymax[nt][e] = mx; mysum[nt][e] = sm;
        }
    }
    if (wm == 1 && gid == 0){
        #pragma unroll
        for (int nt = 0; nt < 4; nt++)
            #pragma unroll
            for (int e = 0; e < 2; e++){
                int j = wn*32 + nt*8 + 2*tig + e;
                pmax[j] = mymax[nt][e]; psum[j] = mysum[nt][e];
            }
    }
    __syncthreads();
    if (wm == 0 && gid == 0){
        #pragma unroll
        for (int nt = 0; nt < 4; nt++)
            #pragma unroll
            for (int e = 0; e < 2; e++){
                int j = wn*32 + nt*8 + 2*tig + e;
                pool_out[j]     = fmaxf(mymax[nt][e], pmax[j]);
                pool_out[D + j] = (mysum[nt][e] + psum[j]) * (1.0f/(float)Lh);
            }
    }
    __syncthreads();

    // LayerNorm over 512 (one element per thread)
    float v = pool_out[t];
    float S  = blockSum512(v,   red, t);
    float SS = blockSum512(v*v, red, t);
    float mean = S  * (1.0f/512.0f);
    float var  = SS * (1.0f/512.0f) - mean*mean;
    float inv  = rsqrtf(var + 1e-5f);
    pool_out[t] = (v - mean)*inv*ln2g[t] + ln2b[t];
    __syncthreads();
}

// ---------------- kernel D: one CTA per (query, support) pair (512 threads) ----------------
__global__ void __launch_bounds__(512, 1) k_pair(
    const float* __restrict__ ln2g, const float* __restrict__ ln2b)
{
    extern __shared__ float sm[];
    float* s_t  = sm + SM_S;
    float* q_t  = sm + SM_Q;
    float* a_t  = sm + SM_A;
    float* att  = sm + SM_ATT;
    float* pmax = sm + SM_PMAX;
    float* psum = sm + SM_PSUM;
    float* pool = sm + SM_POOL;
    float* rmax = sm + SM_RMAX;
    float* rsum = sm + SM_RSUM;
    float* cmax = sm + SM_CMAX;
    float* csum = sm + SM_CSUM;
    float* red  = sm + SM_RED;

    const int m = blockIdx.x;
    const int b = m / (NQh*Nh);
    const int rem = m % (NQh*Nh);
    const int iq = rem / Nh;
    const int n  = rem % Nh;
    const int sIdx = b*Nh + n;      // K = 1
    const int qIdx = b*NQh + iq;
    const int t = threadIdx.x;
    const int lane = t & 31, warp = t >> 5;
    const int gid = lane >> 2, tig = lane & 3;

    // load tiles into pitched smem
    {
        const float* sp = g_sN + (size_t)sIdx*TILE_ELEMS;
        const float* qp = g_qN + (size_t)qIdx*TILE_ELEMS;
        for (int idx = t; idx < TILE_ELEMS; idx += 512){
            int row = idx >> 8, col = idx & 255;
            s_t[row*PITCH + col] = sp[idx];
            q_t[row*PITCH + col] = qp[idx];
        }
    }
    __syncthreads();

    // att[l][k] = s[l] . q[k]  (16 warps: 4x4 tiling of 16x16 output tiles)
    {
        const int wma = warp >> 2, wna = warp & 3;
        float ca[2][4];
        #pragma unroll
        for (int nt = 0; nt < 2; nt++)
            #pragma unroll
            for (int i = 0; i < 4; i++) ca[nt][i] = 0.f;
        for (int kb = 0; kb < 16; kb++){
            unsigned ah[4], al[4];
            int r0 = wma*16 + gid;
            int c0 = kb*16 + 2*tig;
            #pragma unroll
            for (int p = 0; p < 4; p++){
                float2 s2 = *(const float2*)(s_t + (r0 + (p & 1)*8)*PITCH + c0 + (p >> 1)*8);
                split2(s2.x, s2.y, ah[p], al[p]);
            }
            #pragma unroll
            for (int nt = 0; nt < 2; nt++){
                int n0 = wna*16 + nt*8 + gid;
                unsigned bh[2], bl[2];
                float2 q0 = *(const float2*)(q_t + n0*PITCH + c0);
                float2 q1 = *(const float2*)(q_t + n0*PITCH + c0 + 8);
                split2(q0.x, q0.y, bh[0], bl[0]);
                split2(q1.x, q1.y, bh[1], bl[1]);
                mma3(ca[nt], ah, al, bh, bl);
            }
        }
        #pragma unroll
        for (int nt = 0; nt < 2; nt++){
            int r0 = wma*16 + gid;
            int col = wna*16 + nt*8 + 2*tig;
            *(float2*)(att + r0*PA + col)     = make_float2(ca[nt][0], ca[nt][1]);
            *(float2*)(att + (r0+8)*PA + col) = make_float2(ca[nt][2], ca[nt][3]);
        }
    }
    __syncthreads();

    // row maxima (512 threads: 8 per row)
    {
        int row = t >> 3, sub = t & 7;
        const float* rp = att + row*PA + sub*8;
        float mx = fmaxf(fmaxf(fmaxf(rp[0], rp[1]), fmaxf(rp[2], rp[3])),
                         fmaxf(fmaxf(rp[4], rp[5]), fmaxf(rp[6], rp[7])));
        #pragma unroll
        for (int o = 1; o < 8; o <<= 1) mx = fmaxf(mx, __shfl_xor_sync(0xffffffffu, mx, o));
        if (sub == 0) rmax[row] = mx;
    }
    // column maxima (8 per column)
    {
        int col = t >> 3, sub = t & 7;
        float mx = -3.4e38f;
        #pragma unroll
        for (int i = 0; i < 8; i++) mx = fmaxf(mx, att[(sub*8 + i)*PA + col]);
        #pragma unroll
        for (int o = 1; o < 8; o <<= 1) mx = fmaxf(mx, __shfl_xor_sync(0xffffffffu, mx, o));
        if (sub == 0) cmax[col] = mx;
    }
    __syncthreads();

    // att := E = exp(att - rmax[l])
    {
        const int k = t & 63, l0 = t >> 6;   // l0 in 0..7
        #pragma unroll
        for (int i = 0; i < 8; i++){
            int l = l0 + 8*i;
            att[l*PA + k] = __expf(att[l*PA + k] - rmax[l]);
        }
    }
    __syncthreads();

    // row sums (8 threads per row)
    {
        int row = t >> 3, sub = t & 7;
        const float* rp = att + row*PA + sub*8;
        float s = ((rp[0] + rp[1]) + (rp[2] + rp[3])) + ((rp[4] + rp[5]) + (rp[6] + rp[7]));
        #pragma unroll
        for (int o = 1; o < 8; o <<= 1) s += __shfl_xor_sync(0xffffffffu, s, o);
        if (sub == 0) rsum[row] = 1.0f / s;
    }
    // column sums rebased to cmax (8 threads per column)
    {
        int col = t >> 3, sub = t & 7;
        float cm = cmax[col];
        float s = 0.f;
        #pragma unroll
        for (int i = 0; i < 8; i++){
            int l = sub*8 + i;
            float h = __expf(0.5f*(rmax[l] - cm));   // split to avoid overflow
            s += att[l*PA + col] * h * h;
        }
        #pragma unroll
        for (int o = 1; o < 8; o <<= 1) s += __shfl_xor_sync(0xffffffffu, s, o);
        if (sub == 0) csum[col] = 1.0f / s;
    }
    __syncthreads();

    // s_att = (E @ Q) / rowsum  -> a_t
    attn_pv(att, 0, q_t, rsum, a_t, t);
    __syncthreads();

    float c2[2][4][4];
    // c2 = rsum-scaled (E @ Y1_q)   (the a@W1blk contribution)
    attn_y1(att, 0, g_Y1sp + (size_t)(NSUP + qIdx)*8192, rsum, c2, t);

    // phase S -> pool[512..1023]
    proj_phase(s_t, a_t, g_baseF + (size_t)sIdx*4096, c2,
               pmax, psum, pool + 512, ln2g, ln2b, red, t);

    // att := P_col = exp(att_raw - cmax[k]) / colsum
    {
        const int k = t & 63, l0 = t >> 6;
        float ci = csum[k], cm = cmax[k];
        #pragma unroll
        for (int i = 0; i < 8; i++){
            int l = l0 + 8*i;
            float h = __expf(0.5f*(rmax[l] - cm));
            att[l*PA + k] = att[l*PA + k] * h * h * ci;
        }
    }
    __syncthreads();

    // q_att = P_col^T @ S -> a_t
    attn_pv(att, 1, s_t, (const float*)0, a_t, t);
    __syncthreads();

    // c2 = P_col^T @ Y1_s
    attn_y1(att, 1, g_Y1sp + (size_t)sIdx*8192, (const float*)0, c2, t);

    // phase Q -> pool[0..511]
    proj_phase(q_t, a_t, g_baseF + (size_t)(NSUP + qIdx)*4096, c2,
               pmax, psum, pool, ln2g, ln2b, red, t);

    // store pooled cat vector; MLP head handled by k_head
    g_pool[(size_t)m*1024 + t]       = pool[t];
    g_pool[(size_t)m*1024 + 512 + t] = pool[512 + t];
}

// ---------------- kernel H: batched MLP head (8 pairs per block) ----------------
__global__ void __launch_bounds__(256) k_head(
    const float* __restrict__ b1v, const float* __restrict__ W2,
    const float* __restrict__ b2,  const float* __restrict__ W3,
    const float* __restrict__ b3)
{
    __shared__ float ps[8*1024];
    __shared__ float red[8][8];
    int t = threadIdx.x;
    int m0 = blockIdx.x*8;
    for (int i = t; i < 8*1024; i += 256) ps[i] = g_pool[(size_t)m0*1024 + i];
    __syncthreads();
    float acc[8];
    #pragma unroll
    for (int r = 0; r < 8; r++) acc[r] = 0.f;
    #pragma unroll 4
    for (int c = 0; c < 1024; c++){
        float w = g_W1T[c*D + t];
        #pragma unroll
        for (int r = 0; r < 8; r++) acc[r] += ps[r*1024 + c]*w;
    }
    float b1j = b1v[t], w2j = W2[t];
    #pragma unroll
    for (int r = 0; r < 8; r++){
        float part = mishf(acc[r] + b1j) * w2j;
        #pragma unroll
        for (int o = 16; o > 0; o >>= 1) part += __shfl_xor_sync(0xffffffffu, part, o);
        if ((t & 31) == 0) red[r][t >> 5] = part;
    }
    __syncthreads();
    if (t < 8){
        float tot = 0.f;
        #pragma unroll
        for (int w = 0; w < 8; w++) tot += red[t][w];
        g_logits[m0 + t] = mishf(tot + b2[0])*W3[0] + b3[0];
    }
}

// ---------------- kernel E: min-append, logits layout, argmax ----------------
__global__ void k_final(float* __restrict__ out, int out_size){
    int u = threadIdx.x;
    if (u >= Bh*NQh) return;
    float v[Nh];
    float mn = 3.4e38f;
    #pragma unroll
    for (int n2 = 0; n2 < Nh; n2++){
        v[n2] = g_logits[u*Nh + n2];
        mn = fminf(mn, v[n2]);
    }
    if (out_size >= 1100){
        float best = -3.4e38f; int bi = 0;
        #pragma unroll
        for (int n2 = 0; n2 < Nh; n2++){
            out[u*(Nh+1) + n2] = v[n2];
            if (v[n2] > best){ best = v[n2]; bi = n2; }
        }
        out[u*(Nh+1) + Nh] = mn - 1.0f;
        if (out_size >= 1200) out[Bh*NQh*(Nh+1) + u] = (float)bi;
    } else if (out_size == Bh*NQh){
        float best = -3.4e38f; int bi = 0;
        #pragma unroll
        for (int n2 = 0; n2 < Nh; n2++)
            if (v[n2] > best){ best = v[n2]; bi = n2; }
        ((int*)out)[u] = bi;
    }
}

// ---------------- launch ----------------
extern "C" void kernel_launch(void* const* d_in, const int* in_sizes, int n_in,
                              void* d_out, int out_size)
{
    const float* support = (const float*)d_in[0];
    const float* query   = (const float*)d_in[1];
    const float* ln_g    = (const float*)d_in[2];
    const float* ln_b    = (const float*)d_in[3];
    const float* ln2_g   = (const float*)d_in[4];
    const float* ln2_b   = (const float*)d_in[5];
    const float* proj_W  = (const float*)d_in[6];
    const float* proj_b  = (const float*)d_in[7];
    const float* W1      = (const float*)d_in[8];
    const float* b1      = (const float*)d_in[9];
    const float* W2      = (const float*)d_in[10];
    const float* b2      = (const float*)d_in[11];
    const float* W3      = (const float*)d_in[12];
    const float* b3      = (const float*)d_in[13];

    cudaFuncSetAttribute(k_pair, cudaFuncAttributeMaxDynamicSharedMemorySize, SMEM_PAIR_BYTES);
    cudaFuncSetAttribute(k_base, cudaFuncAttributeMaxDynamicSharedMemorySize, SMEM_BASE_BYTES);

    k_ln<<<(NSUP + NQRY)*Lh, 256>>>(support, query, ln_g, ln_b);
    k_transposeW1<<<1024, 256>>>(W1);
    k_prepw<<<256, 256>>>(proj_W);
    k_base<<<NTILE, 256, SMEM_BASE_BYTES>>>(proj_b);
    k_prepY1<<<NTILE*32, 256>>>();
    k_pair<<<Mh, 512, SMEM_PAIR_BYTES>>>(ln2_g, ln2_b);
    k_head<<<Mh/8, 256>>>(b1, W2, b2, W3, b3);
    k_final<<<1, 128>>>((float*)d_out, out_size);
}

// round 7
// speedup vs baseline: 4.5246x; 1.0203x over previous
#include <cuda_runtime.h>
#include <cstdint>

#define D 256
#define Lh 64
#define Bh 2
#define Nh 10
#define NQh 50
#define Mh 1000
#define NSUP 20
#define NQRY 100
#define NTILE 120
#define PITCH 260
#define PA 68
#define TILE_ELEMS (Lh*D)

// ---------------- scratch (device globals; no allocations allowed) ----------------
__device__ float g_sN[NSUP*TILE_ELEMS];
__device__ float g_qN[NQRY*TILE_ELEMS];
__device__ float g_W1T[4*D*D];                    // W1 transposed (for MLP head)
__device__ float4 g_Wm4[16*4*32*32];              // proj_W bf16 hi/lo b-fragments (1MB)
__device__ float4 g_baseF[NTILE*4*32*32];         // base = x@W0^T + b, fragment-native fp32
__device__ float g_Y1f[NTILE*TILE_ELEMS];         // scratch: Y1 = x@W1blk fp32
__device__ uint2 g_Y1sp[NTILE*256*32];            // Y1 split bf16 hi/lo, [tile][d][kpair]
__device__ float g_pool[Mh*1024];                 // pooled+LN'd cat vectors
__device__ float g_logits[Mh];

// Shared-memory layout (floats) for the pair kernel
#define SM_S    0
#define SM_Q    (SM_S + Lh*PITCH)
#define SM_A    (SM_Q + Lh*PITCH)
#define SM_ATT  (SM_A + Lh*PITCH)
#define SM_PMAX (SM_ATT + Lh*PA)
#define SM_PSUM (SM_PMAX + D)
#define SM_POOL (SM_PSUM + D)       // 1024: [0..511]=q_pool, [512..1023]=s_pool
#define SM_RMAX (SM_POOL + 1024)
#define SM_RSUM (SM_RMAX + 64)
#define SM_CMAX (SM_RSUM + 64)
#define SM_CSUM (SM_CMAX + 64)
#define SM_RED  (SM_CSUM + 64)
#define SM_TOTAL (SM_RED + 32)
#define SMEM_PAIR_BYTES (SM_TOTAL*4)
#define SMEM_BASE_BYTES (Lh*PITCH*4)

// ---------------- bf16 split helpers ----------------
__device__ __forceinline__ unsigned pack2(float x0, float x1){
    unsigned r; asm("cvt.rn.bf16x2.f32 %0, %1, %2;" : "=r"(r) : "f"(x1), "f"(x0)); return r;
}
__device__ __forceinline__ void split2(float x0, float x1, unsigned &h, unsigned &l){
    h = pack2(x0, x1);
    float h0 = __uint_as_float(h << 16);
    float h1 = __uint_as_float(h & 0xffff0000u);
    l = pack2(x0 - h0, x1 - h1);
}
__device__ __forceinline__ void mmab(float* c, const unsigned* a, const unsigned* b){
    asm volatile("mma.sync.aligned.m16n8k16.row.col.f32.bf16.bf16.f32 "
        "{%0,%1,%2,%3}, {%4,%5,%6,%7}, {%8,%9}, {%0,%1,%2,%3};\n"
        : "+f"(c[0]), "+f"(c[1]), "+f"(c[2]), "+f"(c[3])
        : "r"(a[0]), "r"(a[1]), "r"(a[2]), "r"(a[3]), "r"(b[0]), "r"(b[1]));
}
__device__ __forceinline__ void mma3(float* c, const unsigned* ah, const unsigned* al,
                                     const unsigned* bh, const unsigned* bl){
    mmab(c, ah, bh); mmab(c, ah, bl); mmab(c, al, bh);
}

// mish(x) = x * tanh(softplus(x)) = x * (u^2+2u)/(u^2+2u+2), u = e^x
__device__ __forceinline__ float mishf(float x){
    if (x > 20.0f) return x;
    float u = __expf(x);
    float v = u*u + 2.0f*u;
    return x * v / (v + 2.0f);
}

// block-wide sum over 512 threads (16 warps)
__device__ __forceinline__ float blockSum512(float v, float* red, int t){
    #pragma unroll
    for (int o = 16; o > 0; o >>= 1) v += __shfl_xor_sync(0xffffffffu, v, o);
    if ((t & 31) == 0) red[t >> 5] = v;
    __syncthreads();
    float s = 0.f;
    #pragma unroll
    for (int w = 0; w < 16; w++) s += red[w];
    __syncthreads();
    return s;
}

// ---------------- kernel A: row LayerNorm of support & query ----------------
__global__ void k_ln(const float* __restrict__ sup, const float* __restrict__ qry,
                     const float* __restrict__ gg, const float* __restrict__ bb){
    __shared__ float rs[8], rq[8];
    int r = blockIdx.x, t = threadIdx.x;
    const float* src; float* dst;
    const int nsr = NSUP*Lh;
    if (r < nsr){ src = sup + (size_t)r*D; dst = g_sN + (size_t)r*D; }
    else        { src = qry + (size_t)(r-nsr)*D; dst = g_qN + (size_t)(r-nsr)*D; }
    float x = src[t];
    float s = x, q = x*x;
    #pragma unroll
    for (int o = 16; o > 0; o >>= 1){
        s += __shfl_xor_sync(0xffffffffu, s, o);
        q += __shfl_xor_sync(0xffffffffu, q, o);
    }
    if ((t & 31) == 0){ rs[t>>5] = s; rq[t>>5] = q; }
    __syncthreads();
    float S = 0.f, Q2 = 0.f;
    #pragma unroll
    for (int w = 0; w < 8; w++){ S += rs[w]; Q2 += rq[w]; }
    float mu  = S  * (1.0f/D);
    float var = Q2 * (1.0f/D) - mu*mu;
    float inv = rsqrtf(var + 1e-5f);
    dst[t] = (x - mu)*inv*gg[t] + bb[t];
}

// ---------------- kernel B: transpose W1 [256][1024] -> [1024][256] ----------------
__global__ void k_transposeW1(const float* __restrict__ W){
    int c = blockIdx.x, j = threadIdx.x;
    g_W1T[c*D + j] = W[(size_t)j*1024 + c];
}

// ---------------- kernel B2: proj_W -> bf16 hi/lo b-fragments ----------------
__global__ void k_prepw(const float* __restrict__ pw){
    int idx = blockIdx.x*256 + threadIdx.x;     // 65536 total
    int lane = idx & 31;
    int jt   = (idx >> 5) & 31;
    int w    = (idx >> 10) & 3;
    int kb   = idx >> 12;
    int tig = lane & 3, gid = lane >> 2;
    int j = jt*8 + gid;
    int cblk = (w == 3) ? 0 : (w + 1);
    size_t base = (size_t)j*1024 + cblk*256 + kb*16 + 2*tig;
    unsigned bh0, bl0, bh1, bl1;
    split2(pw[base],     pw[base + 1], bh0, bl0);
    split2(pw[base + 8], pw[base + 9], bh1, bl1);
    g_Wm4[idx] = make_float4(__uint_as_float(bh0), __uint_as_float(bh1),
                             __uint_as_float(bl0), __uint_as_float(bl1));
}

// ---------------- kernel C: per-tile base (fragment layout) + Y1 = x@W1blk ----------------
__global__ void __launch_bounds__(256,1) k_base(const float* __restrict__ pb){
    extern __shared__ float smx[];
    int tile = blockIdx.x, t = threadIdx.x;
    const float* src = (tile < NSUP) ? (g_sN + (size_t)tile*TILE_ELEMS)
                                     : (g_qN + (size_t)(tile-NSUP)*TILE_ELEMS);
    for (int idx = t; idx < TILE_ELEMS; idx += 256){
        int row = idx >> 8, col = idx & 255;
        smx[row*PITCH + col] = src[idx];
    }
    __syncthreads();

    const int lane = t & 31, warp = t >> 5;
    const int gid = lane >> 2, tig = lane & 3;
    const int wm = warp >> 2, wn = warp & 3;

    // ---- pass 1: base = x @ W0^T + b ----
    {
        float c[2][8][4];
        #pragma unroll
        for (int nt = 0; nt < 8; nt++){
            int col = wn*64 + nt*8 + 2*tig;
            float b0 = pb[col], b1 = pb[col+1];
            #pragma unroll
            for (int mt = 0; mt < 2; mt++){
                c[mt][nt][0] = b0; c[mt][nt][1] = b1;
                c[mt][nt][2] = b0; c[mt][nt][3] = b1;
            }
        }
        for (int kb = 0; kb < 16; kb++){
            float4 wv[8];
            #pragma unroll
            for (int nt = 0; nt < 8; nt++)
                wv[nt] = __ldg(&g_Wm4[((kb*4 + 3)*32 + wn*8 + nt)*32 + lane]);
            unsigned ah[2][4], al[2][4];
            #pragma unroll
            for (int mt = 0; mt < 2; mt++){
                int r0 = wm*32 + mt*16 + gid;
                int c0 = kb*16 + 2*tig;
                #pragma unroll
                for (int p = 0; p < 4; p++){
                    float2 x2 = *(const float2*)(smx + (r0 + (p & 1)*8)*PITCH + c0 + (p >> 1)*8);
                    split2(x2.x, x2.y, ah[mt][p], al[mt][p]);
                }
            }
            #pragma unroll
            for (int nt = 0; nt < 8; nt++){
                unsigned bh[2] = { __float_as_uint(wv[nt].x), __float_as_uint(wv[nt].y) };
                unsigned bl[2] = { __float_as_uint(wv[nt].z), __float_as_uint(wv[nt].w) };
                mma3(c[0][nt], ah[0], al[0], bh, bl);
                mma3(c[1][nt], ah[1], al[1], bh, bl);
            }
        }
        #pragma unroll
        for (int mt = 0; mt < 2; mt++){
            int r16 = wm*2 + mt;
            #pragma unroll
            for (int nt = 0; nt < 8; nt++){
                int j8 = wn*8 + nt;
                g_baseF[((tile*4 + r16)*32 + j8)*32 + lane] =
                    make_float4(c[mt][nt][0], c[mt][nt][1], c[mt][nt][2], c[mt][nt][3]);
            }
        }
    }

    // ---- pass 2: Y1 = x @ W1blk^T ----
    {
        float c[2][8][4];
        #pragma unroll
        for (int mt = 0; mt < 2; mt++)
            #pragma unroll
            for (int nt = 0; nt < 8; nt++)
                #pragma unroll
                for (int i = 0; i < 4; i++) c[mt][nt][i] = 0.f;
        for (int kb = 0; kb < 16; kb++){
            float4 wv[8];
            #pragma unroll
            for (int nt = 0; nt < 8; nt++)
                wv[nt] = __ldg(&g_Wm4[((kb*4 + 0)*32 + wn*8 + nt)*32 + lane]);
            unsigned ah[2][4], al[2][4];
            #pragma unroll
            for (int mt = 0; mt < 2; mt++){
                int r0 = wm*32 + mt*16 + gid;
                int c0 = kb*16 + 2*tig;
                #pragma unroll
                for (int p = 0; p < 4; p++){
                    float2 x2 = *(const float2*)(smx + (r0 + (p & 1)*8)*PITCH + c0 + (p >> 1)*8);
                    split2(x2.x, x2.y, ah[mt][p], al[mt][p]);
                }
            }
            #pragma unroll
            for (int nt = 0; nt < 8; nt++){
                unsigned bh[2] = { __float_as_uint(wv[nt].x), __float_as_uint(wv[nt].y) };
                unsigned bl[2] = { __float_as_uint(wv[nt].z), __float_as_uint(wv[nt].w) };
                mma3(c[0][nt], ah[0], al[0], bh, bl);
                mma3(c[1][nt], ah[1], al[1], bh, bl);
            }
        }
        float* dst = g_Y1f + (size_t)tile*TILE_ELEMS;
        #pragma unroll
        for (int mt = 0; mt < 2; mt++){
            int r0 = wm*32 + mt*16 + gid;
            #pragma unroll
            for (int nt = 0; nt < 8; nt++){
                int col = wn*64 + nt*8 + 2*tig;
                *(float2*)(dst + r0*D + col)     = make_float2(c[mt][nt][0], c[mt][nt][1]);
                *(float2*)(dst + (r0+8)*D + col) = make_float2(c[mt][nt][2], c[mt][nt][3]);
            }
        }
    }
}

// ---------------- kernel C2: split Y1 along seq dim -> g_Y1sp[tile][d][kpair] ----------------
__global__ void k_prepY1(){
    int idx = blockIdx.x*256 + threadIdx.x;   // NTILE*8192
    int tile = idx >> 13;
    int rem  = idx & 8191;
    int d  = rem >> 5;
    int kp = rem & 31;
    const float* Y = g_Y1f + (size_t)tile*TILE_ELEMS;
    float y0 = Y[(2*kp)*D + d];
    float y1 = Y[(2*kp+1)*D + d];
    unsigned h, l; split2(y0, y1, h, l);
    g_Y1sp[idx] = make_uint2(h, l);
}

// ---------------- merged attention GEMM: pv (out -> a_t) AND y1 (c2 regs) ----------------
// out[64,256] = A[64,64] * B[64,256];  c2 = A[64,64] @ Y1[64,256] in proj fragment layout
// transA=0: A[m][k] = attm[m*PA + k];  transA=1: A[m][k] = attm[k*PA + m]
__device__ __forceinline__ void attn_pv_y1(const float* __restrict__ attm, int transA,
                                           const float* __restrict__ Btile,
                                           const uint2* __restrict__ y1sp,
                                           const float* __restrict__ rscale,
                                           float* __restrict__ out,
                                           float c2[2][4][4], int t){
    const int lane = t & 31, warp = t >> 5;
    const int gid = lane >> 2, tig = lane & 3;
    const int wm = warp >> 3, wn = warp & 7;
    float c[2][4][4];
    #pragma unroll
    for (int mt = 0; mt < 2; mt++)
        #pragma unroll
        for (int nt = 0; nt < 4; nt++)
            #pragma unroll
            for (int i = 0; i < 4; i++){ c[mt][nt][i] = 0.f; c2[mt][nt][i] = 0.f; }

    for (int kb = 0; kb < 4; kb++){
        // prefetch y1 fragments (L2 LDG) at top of body
        uint2 u0[4], u1[4];
        #pragma unroll
        for (int nt = 0; nt < 4; nt++){
            int d0 = wn*32 + nt*8 + gid;
            int kp = kb*8 + tig;
            u0[nt] = __ldg(&y1sp[d0*32 + kp]);
            u1[nt] = __ldg(&y1sp[d0*32 + kp + 4]);
        }
        // shared A-splits
        unsigned ah[2][4], al[2][4];
        #pragma unroll
        for (int mt = 0; mt < 2; mt++){
            int r0 = wm*32 + mt*16 + gid;
            int c0 = kb*16 + 2*tig;
            #pragma unroll
            for (int p = 0; p < 4; p++){
                int rr = r0 + (p & 1)*8;
                int cc = c0 + (p >> 1)*8;
                float v0, v1;
                if (transA){ v0 = attm[cc*PA + rr]; v1 = attm[(cc+1)*PA + rr]; }
                else { float2 v = *(const float2*)(attm + rr*PA + cc); v0 = v.x; v1 = v.y; }
                split2(v0, v1, ah[mt][p], al[mt][p]);
            }
        }
        // pv mma (B from smem)
        #pragma unroll
        for (int nt = 0; nt < 4; nt++){
            int d0 = wn*32 + nt*8 + gid;
            int k0 = kb*16 + 2*tig;
            unsigned bh[2], bl[2];
            split2(Btile[k0*PITCH + d0],     Btile[(k0+1)*PITCH + d0], bh[0], bl[0]);
            split2(Btile[(k0+8)*PITCH + d0], Btile[(k0+9)*PITCH + d0], bh[1], bl[1]);
            mma3(c[0][nt], ah[0], al[0], bh, bl);
            mma3(c[1][nt], ah[1], al[1], bh, bl);
        }
        // y1 mma (B prefetched)
        #pragma unroll
        for (int nt = 0; nt < 4; nt++){
            unsigned bh[2] = { u0[nt].x, u1[nt].x };
            unsigned bl[2] = { u0[nt].y, u1[nt].y };
            mma3(c2[0][nt], ah[0], al[0], bh, bl);
            mma3(c2[1][nt], ah[1], al[1], bh, bl);
        }
    }
    #pragma unroll
    for (int mt = 0; mt < 2; mt++){
        int r0 = wm*32 + mt*16 + gid;
        float s0 = rscale ? rscale[r0]   : 1.0f;
        float s1 = rscale ? rscale[r0+8] : 1.0f;
        #pragma unroll
        for (int nt = 0; nt < 4; nt++){
            int col = wn*32 + nt*8 + 2*tig;
            *(float2*)(out + r0*PITCH + col)     = make_float2(c[mt][nt][0]*s0, c[mt][nt][1]*s0);
            *(float2*)(out + (r0+8)*PITCH + col) = make_float2(c[mt][nt][2]*s1, c[mt][nt][3]*s1);
            c2[mt][nt][0] *= s0; c2[mt][nt][1] *= s0;
            c2[mt][nt][2] *= s1; c2[mt][nt][3] *= s1;
        }
    }
}

// ---------------- enhanced projection (2 features) + mish + pool + LN (512 threads) ----------
__device__ __forceinline__ void proj_phase(
    const float* __restrict__ xt, const float* __restrict__ at,
    const float4* __restrict__ basef, const float c2[2][4][4],
    float* pmax, float* psum, float* pool_out,
    const float* __restrict__ ln2g, const float* __restrict__ ln2b,
    float* red, int t)
{
    const int lane = t & 31, warp = t >> 5;
    const int gid = lane >> 2, tig = lane & 3;
    const int wm = warp >> 3, wn = warp & 7;

    float c[2][4][4];
    #pragma unroll
    for (int mt = 0; mt < 2; mt++){
        int r16 = wm*2 + mt;
        #pragma unroll
        for (int nt = 0; nt < 4; nt++){
            int j8 = wn*4 + nt;
            float4 v = __ldg(&basef[(r16*32 + j8)*32 + lane]);
            c[mt][nt][0] = v.x + c2[mt][nt][0];
            c[mt][nt][1] = v.y + c2[mt][nt][1];
            c[mt][nt][2] = v.z + c2[mt][nt][2];
            c[mt][nt][3] = v.w + c2[mt][nt][3];
        }
    }

    for (int kb = 0; kb < 16; kb++){
        // all weight LDGs issued at top of body (L2 latency covered by split work)
        float4 wv1[4], wv2[4];
        #pragma unroll
        for (int nt = 0; nt < 4; nt++){
            int jt = wn*4 + nt;
            wv1[nt] = __ldg(&g_Wm4[((kb*4 + 1)*32 + jt)*32 + lane]);
            wv2[nt] = __ldg(&g_Wm4[((kb*4 + 2)*32 + jt)*32 + lane]);
        }
        float2 xv[2][4], av[2][4];
        #pragma unroll
        for (int mt = 0; mt < 2; mt++){
            int r0 = wm*32 + mt*16 + gid;
            int c0 = kb*16 + 2*tig;
            #pragma unroll
            for (int p = 0; p < 4; p++){
                int rr = r0 + (p & 1)*8;
                int cc = c0 + (p >> 1)*8;
                xv[mt][p] = *(const float2*)(xt + rr*PITCH + cc);
                av[mt][p] = *(const float2*)(at + rr*PITCH + cc);
            }
        }
        // feature |x - a|
        {
            unsigned ah[2][4], al[2][4];
            #pragma unroll
            for (int mt = 0; mt < 2; mt++)
                #pragma unroll
                for (int p = 0; p < 4; p++)
                    split2(fabsf(xv[mt][p].x - av[mt][p].x),
                           fabsf(xv[mt][p].y - av[mt][p].y), ah[mt][p], al[mt][p]);
            #pragma unroll
            for (int nt = 0; nt < 4; nt++){
                unsigned bh[2] = { __float_as_uint(wv1[nt].x), __float_as_uint(wv1[nt].y) };
                unsigned bl[2] = { __float_as_uint(wv1[nt].z), __float_as_uint(wv1[nt].w) };
                mma3(c[0][nt], ah[0], al[0], bh, bl);
                mma3(c[1][nt], ah[1], al[1], bh, bl);
            }
        }
        // feature x * a
        {
            unsigned ah[2][4], al[2][4];
            #pragma unroll
            for (int mt = 0; mt < 2; mt++)
                #pragma unroll
                for (int p = 0; p < 4; p++)
                    split2(xv[mt][p].x * av[mt][p].x,
                           xv[mt][p].y * av[mt][p].y, ah[mt][p], al[mt][p]);
            #pragma unroll
            for (int nt = 0; nt < 4; nt++){
                unsigned bh[2] = { __float_as_uint(wv2[nt].x), __float_as_uint(wv2[nt].y) };
                unsigned bl[2] = { __float_as_uint(wv2[nt].z), __float_as_uint(wv2[nt].w) };
                mma3(c[0][nt], ah[0], al[0], bh, bl);
                mma3(c[1][nt], ah[1], al[1], bh, bl);
            }
        }
    }

    // mish + pooled max/sum; warp owns cols wn*32 + nt*8 + 2tig + e, rows wm*32..+31
    float mymax[4][2], mysum[4][2];
    #pragma unroll
    for (int nt = 0; nt < 4; nt++){
        #pragma unroll
        for (int e = 0; e < 2; e++){
            float v00 = mishf(c[0][nt][e]);
            float v01 = mishf(c[0][nt][2+e]);
            float v10 = mishf(c[1][nt][e]);
            float v11 = mishf(c[1][nt][2+e]);
            float mx = fmaxf(fmaxf(v00, v01), fmaxf(v10, v11));
            float sm = (v00 + v01) + (v10 + v11);
            #pragma unroll
            for (int off = 4; off < 32; off <<= 1){
                mx = fmaxf(mx, __shfl_xor_sync(0xffffffffu, mx, off));
                sm += __shfl_xor_sync(0xffffffffu, sm, off);
            }
            mymax[nt][e] = mx; mysum[nt][e] = sm;
        }
    }
    if (wm == 1 && gid == 0){
        #pragma unroll
        for (int nt = 0; nt < 4; nt++)
            #pragma unroll
            for (int e = 0; e < 2; e++){
                int j = wn*32 + nt*8 + 2*tig + e;
                pmax[j] = mymax[nt][e]; psum[j] = mysum[nt][e];
            }
    }
    __syncthreads();
    if (wm == 0 && gid == 0){
        #pragma unroll
        for (int nt = 0; nt < 4; nt++)
            #pragma unroll
            for (int e = 0; e < 2; e++){
                int j = wn*32 + nt*8 + 2*tig + e;
                pool_out[j]     = fmaxf(mymax[nt][e], pmax[j]);
                pool_out[D + j] = (mysum[nt][e] + psum[j]) * (1.0f/(float)Lh);
            }
    }
    __syncthreads();

    // LayerNorm over 512 (one element per thread)
    float v = pool_out[t];
    float S  = blockSum512(v,   red, t);
    float SS = blockSum512(v*v, red, t);
    float mean = S  * (1.0f/512.0f);
    float var  = SS * (1.0f/512.0f) - mean*mean;
    float inv  = rsqrtf(var + 1e-5f);
    pool_out[t] = (v - mean)*inv*ln2g[t] + ln2b[t];
    __syncthreads();
}

// ---------------- kernel D: one CTA per (query, support) pair (512 threads) ----------------
__global__ void __launch_bounds__(512, 1) k_pair(
    const float* __restrict__ ln2g, const float* __restrict__ ln2b)
{
    extern __shared__ float sm[];
    float* s_t  = sm + SM_S;
    float* q_t  = sm + SM_Q;
    float* a_t  = sm + SM_A;
    float* att  = sm + SM_ATT;
    float* pmax = sm + SM_PMAX;
    float* psum = sm + SM_PSUM;
    float* pool = sm + SM_POOL;
    float* rmax = sm + SM_RMAX;
    float* rsum = sm + SM_RSUM;
    float* cmax = sm + SM_CMAX;
    float* csum = sm + SM_CSUM;
    float* red  = sm + SM_RED;

    const int m = blockIdx.x;
    const int b = m / (NQh*Nh);
    const int rem = m % (NQh*Nh);
    const int iq = rem / Nh;
    const int n  = rem % Nh;
    const int sIdx = b*Nh + n;      // K = 1
    const int qIdx = b*NQh + iq;
    const int t = threadIdx.x;
    const int lane = t & 31, warp = t >> 5;
    const int gid = lane >> 2, tig = lane & 3;

    // load tiles into pitched smem
    {
        const float* sp = g_sN + (size_t)sIdx*TILE_ELEMS;
        const float* qp = g_qN + (size_t)qIdx*TILE_ELEMS;
        for (int idx = t; idx < TILE_ELEMS; idx += 512){
            int row = idx >> 8, col = idx & 255;
            s_t[row*PITCH + col] = sp[idx];
            q_t[row*PITCH + col] = qp[idx];
        }
    }
    __syncthreads();

    // att[l][k] = s[l] . q[k]  (16 warps: 4x4 tiling of 16x16 output tiles)
    {
        const int wma = warp >> 2, wna = warp & 3;
        float ca[2][4];
        #pragma unroll
        for (int nt = 0; nt < 2; nt++)
            #pragma unroll
            for (int i = 0; i < 4; i++) ca[nt][i] = 0.f;
        for (int kb = 0; kb < 16; kb++){
            unsigned ah[4], al[4];
            int r0 = wma*16 + gid;
            int c0 = kb*16 + 2*tig;
            #pragma unroll
            for (int p = 0; p < 4; p++){
                float2 s2 = *(const float2*)(s_t + (r0 + (p & 1)*8)*PITCH + c0 + (p >> 1)*8);
                split2(s2.x, s2.y, ah[p], al[p]);
            }
            #pragma unroll
            for (int nt = 0; nt < 2; nt++){
                int n0 = wna*16 + nt*8 + gid;
                unsigned bh[2], bl[2];
                float2 q0 = *(const float2*)(q_t + n0*PITCH + c0);
                float2 q1 = *(const float2*)(q_t + n0*PITCH + c0 + 8);
                split2(q0.x, q0.y, bh[0], bl[0]);
                split2(q1.x, q1.y, bh[1], bl[1]);
                mma3(ca[nt], ah, al, bh, bl);
            }
        }
        #pragma unroll
        for (int nt = 0; nt < 2; nt++){
            int r0 = wma*16 + gid;
            int col = wna*16 + nt*8 + 2*tig;
            *(float2*)(att + r0*PA + col)     = make_float2(ca[nt][0], ca[nt][1]);
            *(float2*)(att + (r0+8)*PA + col) = make_float2(ca[nt][2], ca[nt][3]);
        }
    }
    __syncthreads();

    // row maxima (512 threads: 8 per row)
    {
        int row = t >> 3, sub = t & 7;
        const float* rp = att + row*PA + sub*8;
        float mx = fmaxf(fmaxf(fmaxf(rp[0], rp[1]), fmaxf(rp[2], rp[3])),
                         fmaxf(fmaxf(rp[4], rp[5]), fmaxf(rp[6], rp[7])));
        #pragma unroll
        for (int o = 1; o < 8; o <<= 1) mx = fmaxf(mx, __shfl_xor_sync(0xffffffffu, mx, o));
        if (sub == 0) rmax[row] = mx;
    }
    // column maxima (8 per column)
    {
        int col = t >> 3, sub = t & 7;
        float mx = -3.4e38f;
        #pragma unroll
        for (int i = 0; i < 8; i++) mx = fmaxf(mx, att[(sub*8 + i)*PA + col]);
        #pragma unroll
        for (int o = 1; o < 8; o <<= 1) mx = fmaxf(mx, __shfl_xor_sync(0xffffffffu, mx, o));
        if (sub == 0) cmax[col] = mx;
    }
    __syncthreads();

    // att := E = exp(att - rmax[l])
    {
        const int k = t & 63, l0 = t >> 6;   // l0 in 0..7
        #pragma unroll
        for (int i = 0; i < 8; i++){
            int l = l0 + 8*i;
            att[l*PA + k] = __expf(att[l*PA + k] - rmax[l]);
        }
    }
    __syncthreads();

    // row sums (8 threads per row)
    {
        int row = t >> 3, sub = t & 7;
        const float* rp = att + row*PA + sub*8;
        float s = ((rp[0] + rp[1]) + (rp[2] + rp[3])) + ((rp[4] + rp[5]) + (rp[6] + rp[7]));
        #pragma unroll
        for (int o = 1; o < 8; o <<= 1) s += __shfl_xor_sync(0xffffffffu, s, o);
        if (sub == 0) rsum[row] = 1.0f / s;
    }
    // column sums rebased to cmax (8 threads per column)
    {
        int col = t >> 3, sub = t & 7;
        float cm = cmax[col];
        float s = 0.f;
        #pragma unroll
        for (int i = 0; i < 8; i++){
            int l = sub*8 + i;
            float h = __expf(0.5f*(rmax[l] - cm));   // split to avoid overflow
            s += att[l*PA + col] * h * h;
        }
        #pragma unroll
        for (int o = 1; o < 8; o <<= 1) s += __shfl_xor_sync(0xffffffffu, s, o);
        if (sub == 0) csum[col] = 1.0f / s;
    }
    __syncthreads();

    float c2[2][4][4];
    // s_att = (E @ Q) / rowsum -> a_t;  c2 = rsum-scaled (E @ Y1_q)
    attn_pv_y1(att, 0, q_t, g_Y1sp + (size_t)(NSUP + qIdx)*8192, rsum, a_t, c2, t);
    __syncthreads();

    // phase S -> pool[512..1023]
    proj_phase(s_t, a_t, g_baseF + (size_t)sIdx*4096, c2,
               pmax, psum, pool + 512, ln2g, ln2b, red, t);

    // att := P_col = exp(att_raw - cmax[k]) / colsum
    {
        const int k = t & 63, l0 = t >> 6;
        float ci = csum[k], cm = cmax[k];
        #pragma unroll
        for (int i = 0; i < 8; i++){
            int l = l0 + 8*i;
            float h = __expf(0.5f*(rmax[l] - cm));
            att[l*PA + k] = att[l*PA + k] * h * h * ci;
        }
    }
    __syncthreads();

    // q_att = P_col^T @ S -> a_t;  c2 = P_col^T @ Y1_s
    attn_pv_y1(att, 1, s_t, g_Y1sp + (size_t)sIdx*8192, (const float*)0, a_t, c2, t);
    __syncthreads();

    // phase Q -> pool[0..511]
    proj_phase(q_t, a_t, g_baseF + (size_t)(NSUP + qIdx)*4096, c2,
               pmax, psum, pool, ln2g, ln2b, red, t);

    // store pooled cat vector; MLP head handled by k_head
    g_pool[(size_t)m*1024 + t]       = pool[t];
    g_pool[(size_t)m*1024 + 512 + t] = pool[512 + t];
}

// ---------------- kernel H: batched MLP head (8 pairs per block) ----------------
__global__ void __launch_bounds__(256) k_head(
    const float* __restrict__ b1v, const float* __restrict__ W2,
    const float* __restrict__ b2,  const float* __restrict__ W3,
    const float* __restrict__ b3)
{
    __shared__ float ps[8*1024];
    __shared__ float red[8][8];
    int t = threadIdx.x;
    int m0 = blockIdx.x*8;
    for (int i = t; i < 8*1024; i += 256) ps[i] = g_pool[(size_t)m0*1024 + i];
    __syncthreads();
    float acc[8];
    #pragma unroll
    for (int r = 0; r < 8; r++) acc[r] = 0.f;
    #pragma unroll 4
    for (int c = 0; c < 1024; c++){
        float w = g_W1T[c*D + t];
        #pragma unroll
        for (int r = 0; r < 8; r++) acc[r] += ps[r*1024 + c]*w;
    }
    float b1j = b1v[t], w2j = W2[t];
    #pragma unroll
    for (int r = 0; r < 8; r++){
        float part = mishf(acc[r] + b1j) * w2j;
        #pragma unroll
        for (int o = 16; o > 0; o >>= 1) part += __shfl_xor_sync(0xffffffffu, part, o);
        if ((t & 31) == 0) red[r][t >> 5] = part;
    }
    __syncthreads();
    if (t < 8){
        float tot = 0.f;
        #pragma unroll
        for (int w = 0; w < 8; w++) tot += red[t][w];
        g_logits[m0 + t] = mishf(tot + b2[0])*W3[0] + b3[0];
    }
}

// ---------------- kernel E: min-append, logits layout, argmax ----------------
__global__ void k_final(float* __restrict__ out, int out_size){
    int u = threadIdx.x;
    if (u >= Bh*NQh) return;
    float v[Nh];
    float mn = 3.4e38f;
    #pragma unroll
    for (int n2 = 0; n2 < Nh; n2++){
        v[n2] = g_logits[u*Nh + n2];
        mn = fminf(mn, v[n2]);
    }
    if (out_size >= 1100){
        float best = -3.4e38f; int bi = 0;
        #pragma unroll
        for (int n2 = 0; n2 < Nh; n2++){
            out[u*(Nh+1) + n2] = v[n2];
            if (v[n2] > best){ best = v[n2]; bi = n2; }
        }
        out[u*(Nh+1) + Nh] = mn - 1.0f;
        if (out_size >= 1200) out[Bh*NQh*(Nh+1) + u] = (float)bi;
    } else if (out_size == Bh*NQh){
        float best = -3.4e38f; int bi = 0;
        #pragma unroll
        for (int n2 = 0; n2 < Nh; n2++)
            if (v[n2] > best){ best = v[n2]; bi = n2; }
        ((int*)out)[u] = bi;
    }
}

// ---------------- launch ----------------
extern "C" void kernel_launch(void* const* d_in, const int* in_sizes, int n_in,
                              void* d_out, int out_size)
{
    const float* support = (const float*)d_in[0];
    const float* query   = (const float*)d_in[1];
    const float* ln_g    = (const float*)d_in[2];
    const float* ln_b    = (const float*)d_in[3];
    const float* ln2_g   = (const float*)d_in[4];
    const float* ln2_b   = (const float*)d_in[5];
    const float* proj_W  = (const float*)d_in[6];
    const float* proj_b  = (const float*)d_in[7];
    const float* W1      = (const float*)d_in[8];
    const float* b1      = (const float*)d_in[9];
    const float* W2      = (const float*)d_in[10];
    const float* b2      = (const float*)d_in[11];
    const float* W3      = (const float*)d_in[12];
    const float* b3      = (const float*)d_in[13];

    cudaFuncSetAttribute(k_pair, cudaFuncAttributeMaxDynamicSharedMemorySize, SMEM_PAIR_BYTES);
    cudaFuncSetAttribute(k_base, cudaFuncAttributeMaxDynamicSharedMemorySize, SMEM_BASE_BYTES);

    k_ln<<<(NSUP + NQRY)*Lh, 256>>>(support, query, ln_g, ln_b);
    k_transposeW1<<<1024, 256>>>(W1);
    k_prepw<<<256, 256>>>(proj_W);
    k_base<<<NTILE, 256, SMEM_BASE_BYTES>>>(proj_b);
    k_prepY1<<<NTILE*32, 256>>>();
    k_pair<<<Mh, 512, SMEM_PAIR_BYTES>>>(ln2_g, ln2_b);
    k_head<<<Mh/8, 256>>>(b1, W2, b2, W3, b3);
    k_final<<<1, 128>>>((float*)d_out, out_size);
}